// round 1
// baseline (speedup 1.0000x reference)
#include <cuda_runtime.h>
#include <cuda_bf16.h>
#include <math.h>

// ---------------------------------------------------------------------------
// Problem constants
//   C=768, NUM_HEADS=12, D=64, HID=3072, HP=WP=14, TF=8, BATCH=4
//   N = 1 + 14*14*8 = 1569
//   temporal tokens MT = 4*196*8 = 6272
//   spatial tokens  MS = 32*197  = 6304
//   full tokens     MX = 4*1569  = 6276
// ---------------------------------------------------------------------------
#define CC     768
#define C3     2304
#define NH     12
#define HD     64
#define HIDDEN 3072
#define TT     8
#define HW     196
#define BB     4
#define NTOK   1569
#define MT     6272
#define MS     6304
#define MX     6276
#define SL     197
#define SB     32          // B*T spatial batches
#define ZB     (SB*NH)     // 384 (seq,head) pairs
#define SL2    (SL*SL)     // 38809

// ---------------------------------------------------------------------------
// Static device scratch (allocation-free rule)
// ---------------------------------------------------------------------------
__device__ float g_ln  [(long)MS * CC];       // LN outputs (reused 3x)
__device__ float g_qkv [(long)MS * C3];       // qkv (reused temporal/spatial)
__device__ float g_attn[(long)MS * CC];       // attention outputs
__device__ float g_proj[(long)MS * CC];       // proj outputs
__device__ float g_xt  [(long)MT * CC];       // xt after temporal residual
__device__ float g_sc  [(long)ZB * SL2];      // spatial attention scores
__device__ float g_fc1 [(long)MX * HIDDEN];   // MLP hidden (after gelu)

__device__ __forceinline__ float gelu_exact(float v) {
    return 0.5f * v * (1.0f + erff(v * 0.7071067811865475f));
}

// ---------------------------------------------------------------------------
// Generic NT SGEMM:  C[M,N] = A[M,K] * B[N,K]^T + bias  (+epilogue)
//   EPI 0: +bias
//   EPI 1: gelu(+bias)
//   EPI 2: +bias + resid[(m + m/1568 + 1)*768 + n]   (skip-cls residual from x)
//   EPI 3: +bias + C[m,n]                            (in-place residual add)
// Tile 64x64x16, 256 threads, 4x4 microtile.
// ---------------------------------------------------------------------------
template<int EPI>
__global__ void gemm_nt(const float* __restrict__ A, int lda,
                        const float* __restrict__ Bw, int ldb,
                        const float* __restrict__ bias,
                        float* __restrict__ Cm, int ldc,
                        const float* __restrict__ resid,
                        int M, int N, int K)
{
    __shared__ float As[16][68];
    __shared__ float Bs[16][68];
    const int tid = threadIdx.x;
    const int tx = tid & 15, ty = tid >> 4;
    const int row0 = blockIdx.y * 64, col0 = blockIdx.x * 64;
    float acc[4][4] = {};
    const int lr = tid >> 2;          // 0..63
    const int lc = (tid & 3) << 2;    // 0,4,8,12

    for (int k0 = 0; k0 < K; k0 += 16) {
        #pragma unroll
        for (int u = 0; u < 4; u++) {
            int gc = k0 + lc + u;
            int gr = row0 + lr;
            As[lc + u][lr] = (gr < M && gc < K) ? A[(long)gr * lda + gc] : 0.0f;
            int hr = col0 + lr;
            Bs[lc + u][lr] = (hr < N && gc < K) ? Bw[(long)hr * ldb + gc] : 0.0f;
        }
        __syncthreads();
        #pragma unroll
        for (int kk = 0; kk < 16; kk++) {
            float a[4], b[4];
            #pragma unroll
            for (int i = 0; i < 4; i++) a[i] = As[kk][ty * 4 + i];
            #pragma unroll
            for (int j = 0; j < 4; j++) b[j] = Bs[kk][tx * 4 + j];
            #pragma unroll
            for (int i = 0; i < 4; i++)
                #pragma unroll
                for (int j = 0; j < 4; j++)
                    acc[i][j] = fmaf(a[i], b[j], acc[i][j]);
        }
        __syncthreads();
    }

    #pragma unroll
    for (int i = 0; i < 4; i++) {
        int m = row0 + ty * 4 + i;
        if (m >= M) continue;
        #pragma unroll
        for (int j = 0; j < 4; j++) {
            int n = col0 + tx * 4 + j;
            if (n >= N) continue;
            float v = acc[i][j] + bias[n];
            if (EPI == 1) v = gelu_exact(v);
            if (EPI == 2) v += resid[(long)(m + m / 1568 + 1) * CC + n];
            if (EPI == 3) v += Cm[(long)m * ldc + n];
            Cm[(long)m * ldc + n] = v;
        }
    }
}

// ---------------------------------------------------------------------------
// LayerNorm over last dim (768 = 256*3). One block per row.
//   mode 0: src row = x[(m + m/1568 + 1)]          (temporal, skip cls)
//   mode 1: spatial gather from {x cls row, g_xt}  (build xs rows)
//   mode 2: src row = src0[m]
// ---------------------------------------------------------------------------
__global__ void ln_kernel(const float* __restrict__ src0,
                          const float* __restrict__ xt,
                          const float* __restrict__ g,
                          const float* __restrict__ bta,
                          float* __restrict__ out, int mode)
{
    int m = blockIdx.x;
    const float* src;
    if (mode == 0) {
        src = src0 + (long)(m + m / 1568 + 1) * CC;
    } else if (mode == 1) {
        int sb = m / SL, p = m % SL;
        int b = sb >> 3, t = sb & 7;
        if (p == 0) src = src0 + (long)b * NTOK * CC;                 // init_cls
        else        src = xt + ((long)(b * HW + (p - 1)) * TT + t) * CC;
    } else {
        src = src0 + (long)m * CC;
    }
    int tid = threadIdx.x;
    float v0 = src[tid], v1 = src[tid + 256], v2 = src[tid + 512];
    float s = v0 + v1 + v2;
    __shared__ float sh[32];
    int lane = tid & 31, wid = tid >> 5;
    #pragma unroll
    for (int o = 16; o; o >>= 1) s += __shfl_xor_sync(0xffffffffu, s, o);
    if (lane == 0) sh[wid] = s;
    __syncthreads();
    if (wid == 0) {
        float t2 = (lane < 8) ? sh[lane] : 0.0f;
        #pragma unroll
        for (int o = 4; o; o >>= 1) t2 += __shfl_xor_sync(0xffffffffu, t2, o);
        if (lane == 0) sh[0] = t2;
    }
    __syncthreads();
    float mean = sh[0] * (1.0f / 768.0f);
    __syncthreads();
    float d0 = v0 - mean, d1 = v1 - mean, d2 = v2 - mean;
    float s2 = d0 * d0 + d1 * d1 + d2 * d2;
    #pragma unroll
    for (int o = 16; o; o >>= 1) s2 += __shfl_xor_sync(0xffffffffu, s2, o);
    if (lane == 0) sh[wid] = s2;
    __syncthreads();
    if (wid == 0) {
        float t2 = (lane < 8) ? sh[lane] : 0.0f;
        #pragma unroll
        for (int o = 4; o; o >>= 1) t2 += __shfl_xor_sync(0xffffffffu, t2, o);
        if (lane == 0) sh[0] = t2;
    }
    __syncthreads();
    float inv = rsqrtf(sh[0] * (1.0f / 768.0f) + 1e-5f);
    long ob = (long)m * CC;
    out[ob + tid]       = d0 * inv * g[tid]       + bta[tid];
    out[ob + tid + 256] = d1 * inv * g[tid + 256] + bta[tid + 256];
    out[ob + tid + 512] = d2 * inv * g[tid + 512] + bta[tid + 512];
}

// ---------------------------------------------------------------------------
// Temporal attention: fully fused per (seq, head). seq len 8, D=64.
// grid (784, 12), 64 threads.
// ---------------------------------------------------------------------------
__global__ void temporal_attn(const float* __restrict__ qkv, float* __restrict__ out)
{
    int seq = blockIdx.x, h = blockIdx.y;
    __shared__ float q[TT][HD], k[TT][HD], v[TT][HD], p[TT][TT];
    int tid = threadIdx.x;  // 0..63 = d
    long base = (long)(seq * TT) * C3 + h * HD;
    #pragma unroll
    for (int t = 0; t < TT; t++) {
        q[t][tid] = qkv[base + (long)t * C3 + tid];
        k[t][tid] = qkv[base + (long)t * C3 + CC + tid];
        v[t][tid] = qkv[base + (long)t * C3 + 2 * CC + tid];
    }
    __syncthreads();
    int i = tid >> 3, j = tid & 7;
    float s = 0.0f;
    #pragma unroll
    for (int d = 0; d < HD; d++) s = fmaf(q[i][d], k[j][d], s);
    p[i][j] = s * 0.125f;   // 1/sqrt(64)
    __syncthreads();
    if (tid < TT) {
        float mx = -1e30f;
        #pragma unroll
        for (int jj = 0; jj < TT; jj++) mx = fmaxf(mx, p[tid][jj]);
        float sum = 0.0f;
        #pragma unroll
        for (int jj = 0; jj < TT; jj++) {
            float e = expf(p[tid][jj] - mx);
            p[tid][jj] = e; sum += e;
        }
        float invs = 1.0f / sum;
        #pragma unroll
        for (int jj = 0; jj < TT; jj++) p[tid][jj] *= invs;
    }
    __syncthreads();
    #pragma unroll
    for (int t = 0; t < TT; t++) {
        float o = 0.0f;
        #pragma unroll
        for (int jj = 0; jj < TT; jj++) o = fmaf(p[t][jj], v[jj][tid], o);
        out[(long)(seq * TT + t) * CC + h * HD + tid] = o;
    }
}

// ---------------------------------------------------------------------------
// Spatial scores: per z=(s,h): S = Q * K^T,  197x197x64. Tile 32x32x16.
// grid (7, 7, 384), 256 threads, 2x2 microtile.
// ---------------------------------------------------------------------------
__global__ void spatial_scores(const float* __restrict__ qkv, float* __restrict__ sc)
{
    int z = blockIdx.z, s = z / NH, h = z % NH;
    const float* Q  = qkv + (long)s * SL * C3 + h * HD;
    const float* Kp = Q + CC;
    float* S = sc + (long)z * SL2;
    __shared__ float Qs[16][34], Ks[16][34];
    int tid = threadIdx.x;
    int tx = tid & 15, ty = tid >> 4;
    int row0 = blockIdx.y * 32, col0 = blockIdx.x * 32;
    float acc[2][2] = {};
    int lr = tid >> 3;          // 0..31
    int lc = (tid & 7) << 1;    // 0,2,...,14
    for (int k0 = 0; k0 < HD; k0 += 16) {
        #pragma unroll
        for (int u = 0; u < 2; u++) {
            int gr = row0 + lr;
            Qs[lc + u][lr] = (gr < SL) ? Q[(long)gr * C3 + k0 + lc + u] : 0.0f;
            int gc = col0 + lr;
            Ks[lc + u][lr] = (gc < SL) ? Kp[(long)gc * C3 + k0 + lc + u] : 0.0f;
        }
        __syncthreads();
        #pragma unroll
        for (int kk = 0; kk < 16; kk++) {
            float a0 = Qs[kk][ty * 2], a1 = Qs[kk][ty * 2 + 1];
            float b0 = Ks[kk][tx * 2], b1 = Ks[kk][tx * 2 + 1];
            acc[0][0] = fmaf(a0, b0, acc[0][0]);
            acc[0][1] = fmaf(a0, b1, acc[0][1]);
            acc[1][0] = fmaf(a1, b0, acc[1][0]);
            acc[1][1] = fmaf(a1, b1, acc[1][1]);
        }
        __syncthreads();
    }
    #pragma unroll
    for (int i = 0; i < 2; i++) {
        int m = row0 + ty * 2 + i;
        if (m >= SL) continue;
        #pragma unroll
        for (int j = 0; j < 2; j++) {
            int n = col0 + tx * 2 + j;
            if (n < SL) S[(long)m * SL + n] = acc[i][j];
        }
    }
}

// ---------------------------------------------------------------------------
// Softmax over rows of length 197, with 1/8 scale folded in.
// One warp per row, 8 rows per block.
// ---------------------------------------------------------------------------
__global__ void softmax197(float* __restrict__ sc, int nrows)
{
    int row = blockIdx.x * 8 + (threadIdx.x >> 5);
    if (row >= nrows) return;
    int lane = threadIdx.x & 31;
    float* r = sc + (long)row * SL;
    float mx = -1e30f;
    for (int j = lane; j < SL; j += 32) mx = fmaxf(mx, r[j] * 0.125f);
    #pragma unroll
    for (int o = 16; o; o >>= 1) mx = fmaxf(mx, __shfl_xor_sync(0xffffffffu, mx, o));
    float sum = 0.0f;
    for (int j = lane; j < SL; j += 32) {
        float e = expf(r[j] * 0.125f - mx);
        r[j] = e; sum += e;
    }
    #pragma unroll
    for (int o = 16; o; o >>= 1) sum += __shfl_xor_sync(0xffffffffu, sum, o);
    float inv = 1.0f / sum;
    for (int j = lane; j < SL; j += 32) r[j] *= inv;
}

// ---------------------------------------------------------------------------
// Spatial P*V: per z=(s,h): O = P(197x197) * V(197x64). Tile 32x64x16.
// grid (1, 7, 384), 256 threads, 2x4 microtile.
// ---------------------------------------------------------------------------
__global__ void spatial_pv(const float* __restrict__ sc, const float* __restrict__ qkv,
                           float* __restrict__ out)
{
    int z = blockIdx.z, s = z / NH, h = z % NH;
    const float* P = sc + (long)z * SL2;
    const float* V = qkv + (long)s * SL * C3 + 2 * CC + h * HD;
    float* O = out + (long)s * SL * CC + h * HD;
    __shared__ float Ps[16][34], Vs[16][66];
    int tid = threadIdx.x;
    int tx = tid & 15, ty = tid >> 4;
    int row0 = blockIdx.y * 32;
    float acc[2][4] = {};
    int lrp = tid >> 3, lcp = (tid & 7) << 1;   // P tile: 32x16
    int lrv = tid >> 4, lcv = (tid & 15) << 2;  // V tile: 16x64
    for (int k0 = 0; k0 < SL; k0 += 16) {
        #pragma unroll
        for (int u = 0; u < 2; u++) {
            int gm = row0 + lrp, gk = k0 + lcp + u;
            Ps[lcp + u][lrp] = (gm < SL && gk < SL) ? P[(long)gm * SL + gk] : 0.0f;
        }
        {
            int gk = k0 + lrv;
            #pragma unroll
            for (int u = 0; u < 4; u++)
                Vs[lrv][lcv + u] = (gk < SL) ? V[(long)gk * C3 + lcv + u] : 0.0f;
        }
        __syncthreads();
        #pragma unroll
        for (int kk = 0; kk < 16; kk++) {
            float a0 = Ps[kk][ty * 2], a1 = Ps[kk][ty * 2 + 1];
            float b[4];
            #pragma unroll
            for (int j = 0; j < 4; j++) b[j] = Vs[kk][tx * 4 + j];
            #pragma unroll
            for (int j = 0; j < 4; j++) {
                acc[0][j] = fmaf(a0, b[j], acc[0][j]);
                acc[1][j] = fmaf(a1, b[j], acc[1][j]);
            }
        }
        __syncthreads();
    }
    #pragma unroll
    for (int i = 0; i < 2; i++) {
        int m = row0 + ty * 2 + i;
        if (m >= SL) continue;
        #pragma unroll
        for (int j = 0; j < 4; j++)
            O[(long)m * CC + tx * 4 + j] = acc[i][j];
    }
}

// ---------------------------------------------------------------------------
// Assemble: x_new = concat(init_cls, xt) + concat(cls_out, res_s scatter)
// One block per output row (6276), 256 threads.
// ---------------------------------------------------------------------------
__global__ void assemble(const float* __restrict__ x, const float* __restrict__ xt,
                         const float* __restrict__ ps, float* __restrict__ out)
{
    int row = blockIdx.x;
    int b = row / NTOK, n = row % NTOK;
    long orow = (long)row * CC;
    if (n == 0) {
        for (int c = threadIdx.x; c < CC; c += 256) {
            float acc = 0.0f;
            #pragma unroll
            for (int t = 0; t < TT; t++)
                acc += ps[((long)(b * TT + t) * SL) * CC + c];
            out[orow + c] = x[orow + c] + acc * 0.125f;
        }
    } else {
        int r = n - 1, hw = r >> 3, t = r & 7;
        long xtrow = ((long)b * 1568 + r) * CC;
        long psrow = ((long)((b * TT + t) * SL + 1 + hw)) * CC;
        for (int c = threadIdx.x; c < CC; c += 256)
            out[orow + c] = xt[xtrow + c] + ps[psrow + c];
    }
}

// ---------------------------------------------------------------------------
// Host launch
// ---------------------------------------------------------------------------
extern "C" void kernel_launch(void* const* d_in, const int* in_sizes, int n_in,
                              void* d_out, int out_size)
{
    const float* x        = (const float*)d_in[0];
    const float* ln_t_g   = (const float*)d_in[1];
    const float* ln_t_b   = (const float*)d_in[2];
    const float* t_qkv_w  = (const float*)d_in[3];
    const float* t_qkv_b  = (const float*)d_in[4];
    const float* t_proj_w = (const float*)d_in[5];
    const float* t_proj_b = (const float*)d_in[6];
    const float* t_fc_w   = (const float*)d_in[7];
    const float* t_fc_b   = (const float*)d_in[8];
    const float* ln1_g    = (const float*)d_in[9];
    const float* ln1_b    = (const float*)d_in[10];
    const float* s_qkv_w  = (const float*)d_in[11];
    const float* s_qkv_b  = (const float*)d_in[12];
    const float* s_proj_w = (const float*)d_in[13];
    const float* s_proj_b = (const float*)d_in[14];
    const float* ln2_g    = (const float*)d_in[15];
    const float* ln2_b    = (const float*)d_in[16];
    const float* fc1_w    = (const float*)d_in[17];
    const float* fc1_b    = (const float*)d_in[18];
    const float* fc2_w    = (const float*)d_in[19];
    const float* fc2_b    = (const float*)d_in[20];
    float* out = (float*)d_out;

    float *ln, *qkv, *attn, *proj, *xt, *sc, *fc1;
    cudaGetSymbolAddress((void**)&ln,   g_ln);
    cudaGetSymbolAddress((void**)&qkv,  g_qkv);
    cudaGetSymbolAddress((void**)&attn, g_attn);
    cudaGetSymbolAddress((void**)&proj, g_proj);
    cudaGetSymbolAddress((void**)&xt,   g_xt);
    cudaGetSymbolAddress((void**)&sc,   g_sc);
    cudaGetSymbolAddress((void**)&fc1,  g_fc1);

    // 1. temporal LN (skip cls)
    ln_kernel<<<MT, 256>>>(x, nullptr, ln_t_g, ln_t_b, ln, 0);

    // 2. temporal qkv: 6272 x 2304 x 768
    {
        dim3 g((C3 + 63) / 64, (MT + 63) / 64);
        gemm_nt<0><<<g, 256>>>(ln, CC, t_qkv_w, CC, t_qkv_b, qkv, C3, nullptr, MT, C3, CC);
    }

    // 3. temporal attention
    temporal_attn<<<dim3(BB * HW, NH), 64>>>(qkv, attn);

    // 4. temporal proj: 6272 x 768 x 768
    {
        dim3 g((CC + 63) / 64, (MT + 63) / 64);
        gemm_nt<0><<<g, 256>>>(attn, CC, t_proj_w, CC, t_proj_b, proj, CC, nullptr, MT, CC, CC);
    }

    // 5. t_fc + residual from x (skip-cls): xt = x[:,1:,:] + proj @ t_fc_w.T + b
    {
        dim3 g((CC + 63) / 64, (MT + 63) / 64);
        gemm_nt<2><<<g, 256>>>(proj, CC, t_fc_w, CC, t_fc_b, xt, CC, x, MT, CC, CC);
    }

    // 6. spatial gather + LN1
    ln_kernel<<<MS, 256>>>(x, xt, ln1_g, ln1_b, ln, 1);

    // 7. spatial qkv: 6304 x 2304 x 768
    {
        dim3 g((C3 + 63) / 64, (MS + 63) / 64);
        gemm_nt<0><<<g, 256>>>(ln, CC, s_qkv_w, CC, s_qkv_b, qkv, C3, nullptr, MS, C3, CC);
    }

    // 8-10. spatial attention
    spatial_scores<<<dim3(7, 7, ZB), 256>>>(qkv, sc);
    softmax197<<<(ZB * SL + 7) / 8, 256>>>(sc, ZB * SL);
    spatial_pv<<<dim3(1, 7, ZB), 256>>>(sc, qkv, attn);

    // 11. spatial proj: 6304 x 768 x 768
    {
        dim3 g((CC + 63) / 64, (MS + 63) / 64);
        gemm_nt<0><<<g, 256>>>(attn, CC, s_proj_w, CC, s_proj_b, proj, CC, nullptr, MS, CC, CC);
    }

    // 12. assemble x_new into d_out
    assemble<<<MX, 256>>>(x, xt, proj, out);

    // 13. LN2
    ln_kernel<<<MX, 256>>>(out, nullptr, ln2_g, ln2_b, ln, 2);

    // 14. fc1 + gelu: 6276 x 3072 x 768
    {
        dim3 g((HIDDEN + 63) / 64, (MX + 63) / 64);
        gemm_nt<1><<<g, 256>>>(ln, CC, fc1_w, CC, fc1_b, fc1, HIDDEN, nullptr, MX, HIDDEN, CC);
    }

    // 15. fc2 + in-place residual: d_out = x_new + fc1buf @ fc2_w.T + b
    {
        dim3 g((CC + 63) / 64, (MX + 63) / 64);
        gemm_nt<3><<<g, 256>>>(fc1, HIDDEN, fc2_w, HIDDEN, fc2_b, out, CC, nullptr, MX, CC, HIDDEN);
    }
}

// round 2
// speedup vs baseline: 1.7733x; 1.7733x over previous
#include <cuda_runtime.h>
#include <cuda_bf16.h>
#include <math.h>

// ---------------------------------------------------------------------------
// Problem constants
// ---------------------------------------------------------------------------
#define CC     768
#define C3     2304
#define NH     12
#define HD     64
#define HIDDEN 3072
#define TT     8
#define HW     196
#define BB     4
#define NTOK   1569
#define MT     6272
#define MS     6304
#define MX     6276
#define SL     197
#define SB     32
#define ZB     (SB*NH)
#define SL2    (SL*SL)

// ---------------------------------------------------------------------------
// Static device scratch
// ---------------------------------------------------------------------------
__device__ float g_ln  [(long)MS * CC];
__device__ float g_qkv [(long)MS * C3];
__device__ float g_attn[(long)MS * CC];
__device__ float g_proj[(long)MS * CC];
__device__ float g_xt  [(long)MT * CC];
__device__ float g_sc  [(long)ZB * SL2];
__device__ float g_fc1 [(long)MX * HIDDEN];

__device__ __forceinline__ float gelu_exact(float v) {
    return 0.5f * v * (1.0f + erff(v * 0.7071067811865475f));
}

// ---------------------------------------------------------------------------
// NT SGEMM:  C[M,N] = A[M,K] * B[N,K]^T + bias (+epilogue)
//   EPI 0: +bias
//   EPI 1: gelu(+bias)
//   EPI 2: +bias + resid[(m + m/1568 + 1)*768 + n]
//   EPI 3: +bias + C[m,n]
// Tile 128x128x16, 256 threads, 8x8 microtile (2x2 blocks of 4x4),
// double-buffered smem, float4 LDS.
// Requirements: N % 128 == 0, K % 16 == 0 (true for all call sites).
// ---------------------------------------------------------------------------
#define PADL 132   // 128 + 4, keeps 16B alignment of rows

template<int EPI>
__global__ __launch_bounds__(256, 2)
void gemm_nt(const float* __restrict__ A, int lda,
             const float* __restrict__ Bw, int ldb,
             const float* __restrict__ bias,
             float* __restrict__ Cm, int ldc,
             const float* __restrict__ resid,
             int M, int N, int K)
{
    __shared__ float As[2][16][PADL];
    __shared__ float Bs[2][16][PADL];

    const int tid  = threadIdx.x;
    const int tx   = tid & 15;        // 0..15 -> col groups
    const int ty   = tid >> 4;        // 0..15 -> row groups
    const int row0 = blockIdx.y * 128;
    const int col0 = blockIdx.x * 128;

    // loader mapping: each thread loads one row, 16 consecutive k as 2 float4
    const int lrow = tid >> 1;            // 0..127
    const int lk   = (tid & 1) << 3;      // 0 or 8

    const int arow = min(row0 + lrow, M - 1);   // clamped (branch-free OOB)
    const int brow = col0 + lrow;               // always valid (N%128==0)
    const float* Ap = A  + (long)arow * lda + lk;
    const float* Bp = Bw + (long)brow * ldb + lk;

    float acc[8][8];
    #pragma unroll
    for (int i = 0; i < 8; i++)
        #pragma unroll
        for (int j = 0; j < 8; j++) acc[i][j] = 0.0f;

    const int KT = K >> 4;
    float4 pa0, pa1, pb0, pb1;

    // preload tile 0
    pa0 = *(const float4*)(Ap);
    pa1 = *(const float4*)(Ap + 4);
    pb0 = *(const float4*)(Bp);
    pb1 = *(const float4*)(Bp + 4);
    {
        float* as = &As[0][lk][lrow];
        as[0*PADL] = pa0.x; as[1*PADL] = pa0.y; as[2*PADL] = pa0.z; as[3*PADL] = pa0.w;
        as[4*PADL] = pa1.x; as[5*PADL] = pa1.y; as[6*PADL] = pa1.z; as[7*PADL] = pa1.w;
        float* bs = &Bs[0][lk][lrow];
        bs[0*PADL] = pb0.x; bs[1*PADL] = pb0.y; bs[2*PADL] = pb0.z; bs[3*PADL] = pb0.w;
        bs[4*PADL] = pb1.x; bs[5*PADL] = pb1.y; bs[6*PADL] = pb1.z; bs[7*PADL] = pb1.w;
    }
    __syncthreads();

    for (int kt = 0; kt < KT; kt++) {
        const int cur = kt & 1;
        if (kt + 1 < KT) {
            const float* ap = Ap + (long)(kt + 1) * 16;
            const float* bp = Bp + (long)(kt + 1) * 16;
            pa0 = *(const float4*)(ap);
            pa1 = *(const float4*)(ap + 4);
            pb0 = *(const float4*)(bp);
            pb1 = *(const float4*)(bp + 4);
        }

        #pragma unroll
        for (int kk = 0; kk < 16; kk++) {
            float4 a0 = *(const float4*)&As[cur][kk][ty * 4];
            float4 a1 = *(const float4*)&As[cur][kk][ty * 4 + 64];
            float4 b0 = *(const float4*)&Bs[cur][kk][tx * 4];
            float4 b1 = *(const float4*)&Bs[cur][kk][tx * 4 + 64];
            float av[8] = {a0.x, a0.y, a0.z, a0.w, a1.x, a1.y, a1.z, a1.w};
            float bv[8] = {b0.x, b0.y, b0.z, b0.w, b1.x, b1.y, b1.z, b1.w};
            #pragma unroll
            for (int i = 0; i < 8; i++)
                #pragma unroll
                for (int j = 0; j < 8; j++)
                    acc[i][j] = fmaf(av[i], bv[j], acc[i][j]);
        }

        if (kt + 1 < KT) {
            const int nxt = cur ^ 1;
            float* as = &As[nxt][lk][lrow];
            as[0*PADL] = pa0.x; as[1*PADL] = pa0.y; as[2*PADL] = pa0.z; as[3*PADL] = pa0.w;
            as[4*PADL] = pa1.x; as[5*PADL] = pa1.y; as[6*PADL] = pa1.z; as[7*PADL] = pa1.w;
            float* bs = &Bs[nxt][lk][lrow];
            bs[0*PADL] = pb0.x; bs[1*PADL] = pb0.y; bs[2*PADL] = pb0.z; bs[3*PADL] = pb0.w;
            bs[4*PADL] = pb1.x; bs[5*PADL] = pb1.y; bs[6*PADL] = pb1.z; bs[7*PADL] = pb1.w;
            __syncthreads();
        }
    }

    // epilogue: 8 rows x 2 float4 cols per thread
    #pragma unroll
    for (int i = 0; i < 8; i++) {
        int m = row0 + ty * 4 + ((i < 4) ? i : (64 + i - 4));
        if (m >= M) continue;
        #pragma unroll
        for (int jh = 0; jh < 2; jh++) {
            int n0 = col0 + tx * 4 + jh * 64;
            float v0 = acc[i][jh * 4 + 0] + bias[n0 + 0];
            float v1 = acc[i][jh * 4 + 1] + bias[n0 + 1];
            float v2 = acc[i][jh * 4 + 2] + bias[n0 + 2];
            float v3 = acc[i][jh * 4 + 3] + bias[n0 + 3];
            if (EPI == 1) {
                v0 = gelu_exact(v0); v1 = gelu_exact(v1);
                v2 = gelu_exact(v2); v3 = gelu_exact(v3);
            }
            if (EPI == 2) {
                const float* r = resid + (long)(m + m / 1568 + 1) * CC + n0;
                v0 += r[0]; v1 += r[1]; v2 += r[2]; v3 += r[3];
            }
            if (EPI == 3) {
                float4 old = *(const float4*)(Cm + (long)m * ldc + n0);
                v0 += old.x; v1 += old.y; v2 += old.z; v3 += old.w;
            }
            float4 o = {v0, v1, v2, v3};
            *(float4*)(Cm + (long)m * ldc + n0) = o;
        }
    }
}

// ---------------------------------------------------------------------------
// LayerNorm over last dim (768 = 256*3). One block per row.
// ---------------------------------------------------------------------------
__global__ void ln_kernel(const float* __restrict__ src0,
                          const float* __restrict__ xt,
                          const float* __restrict__ g,
                          const float* __restrict__ bta,
                          float* __restrict__ out, int mode)
{
    int m = blockIdx.x;
    const float* src;
    if (mode == 0) {
        src = src0 + (long)(m + m / 1568 + 1) * CC;
    } else if (mode == 1) {
        int sb = m / SL, p = m % SL;
        int b = sb >> 3, t = sb & 7;
        if (p == 0) src = src0 + (long)b * NTOK * CC;
        else        src = xt + ((long)(b * HW + (p - 1)) * TT + t) * CC;
    } else {
        src = src0 + (long)m * CC;
    }
    int tid = threadIdx.x;
    float v0 = src[tid], v1 = src[tid + 256], v2 = src[tid + 512];
    float s = v0 + v1 + v2;
    __shared__ float sh[32];
    int lane = tid & 31, wid = tid >> 5;
    #pragma unroll
    for (int o = 16; o; o >>= 1) s += __shfl_xor_sync(0xffffffffu, s, o);
    if (lane == 0) sh[wid] = s;
    __syncthreads();
    if (wid == 0) {
        float t2 = (lane < 8) ? sh[lane] : 0.0f;
        #pragma unroll
        for (int o = 4; o; o >>= 1) t2 += __shfl_xor_sync(0xffffffffu, t2, o);
        if (lane == 0) sh[0] = t2;
    }
    __syncthreads();
    float mean = sh[0] * (1.0f / 768.0f);
    __syncthreads();
    float d0 = v0 - mean, d1 = v1 - mean, d2 = v2 - mean;
    float s2 = d0 * d0 + d1 * d1 + d2 * d2;
    #pragma unroll
    for (int o = 16; o; o >>= 1) s2 += __shfl_xor_sync(0xffffffffu, s2, o);
    if (lane == 0) sh[wid] = s2;
    __syncthreads();
    if (wid == 0) {
        float t2 = (lane < 8) ? sh[lane] : 0.0f;
        #pragma unroll
        for (int o = 4; o; o >>= 1) t2 += __shfl_xor_sync(0xffffffffu, t2, o);
        if (lane == 0) sh[0] = t2;
    }
    __syncthreads();
    float inv = rsqrtf(sh[0] * (1.0f / 768.0f) + 1e-5f);
    long ob = (long)m * CC;
    out[ob + tid]       = d0 * inv * g[tid]       + bta[tid];
    out[ob + tid + 256] = d1 * inv * g[tid + 256] + bta[tid + 256];
    out[ob + tid + 512] = d2 * inv * g[tid + 512] + bta[tid + 512];
}

// ---------------------------------------------------------------------------
// Temporal attention: fused per (seq, head). seq len 8, D=64.
// ---------------------------------------------------------------------------
__global__ void temporal_attn(const float* __restrict__ qkv, float* __restrict__ out)
{
    int seq = blockIdx.x, h = blockIdx.y;
    __shared__ float q[TT][HD], k[TT][HD], v[TT][HD], p[TT][TT];
    int tid = threadIdx.x;
    long base = (long)(seq * TT) * C3 + h * HD;
    #pragma unroll
    for (int t = 0; t < TT; t++) {
        q[t][tid] = qkv[base + (long)t * C3 + tid];
        k[t][tid] = qkv[base + (long)t * C3 + CC + tid];
        v[t][tid] = qkv[base + (long)t * C3 + 2 * CC + tid];
    }
    __syncthreads();
    int i = tid >> 3, j = tid & 7;
    float s = 0.0f;
    #pragma unroll
    for (int d = 0; d < HD; d++) s = fmaf(q[i][d], k[j][d], s);
    p[i][j] = s * 0.125f;
    __syncthreads();
    if (tid < TT) {
        float mx = -1e30f;
        #pragma unroll
        for (int jj = 0; jj < TT; jj++) mx = fmaxf(mx, p[tid][jj]);
        float sum = 0.0f;
        #pragma unroll
        for (int jj = 0; jj < TT; jj++) {
            float e = expf(p[tid][jj] - mx);
            p[tid][jj] = e; sum += e;
        }
        float invs = 1.0f / sum;
        #pragma unroll
        for (int jj = 0; jj < TT; jj++) p[tid][jj] *= invs;
    }
    __syncthreads();
    #pragma unroll
    for (int t = 0; t < TT; t++) {
        float o = 0.0f;
        #pragma unroll
        for (int jj = 0; jj < TT; jj++) o = fmaf(p[t][jj], v[jj][tid], o);
        out[(long)(seq * TT + t) * CC + h * HD + tid] = o;
    }
}

// ---------------------------------------------------------------------------
// Spatial scores: per z=(s,h): S = Q * K^T, 197x197x64. Tile 32x32x16.
// ---------------------------------------------------------------------------
__global__ void spatial_scores(const float* __restrict__ qkv, float* __restrict__ sc)
{
    int z = blockIdx.z, s = z / NH, h = z % NH;
    const float* Q  = qkv + (long)s * SL * C3 + h * HD;
    const float* Kp = Q + CC;
    float* S = sc + (long)z * SL2;
    __shared__ float Qs[16][34], Ks[16][34];
    int tid = threadIdx.x;
    int tx = tid & 15, ty = tid >> 4;
    int row0 = blockIdx.y * 32, col0 = blockIdx.x * 32;
    float acc[2][2] = {};
    int lr = tid >> 3;
    int lc = (tid & 7) << 1;
    for (int k0 = 0; k0 < HD; k0 += 16) {
        #pragma unroll
        for (int u = 0; u < 2; u++) {
            int gr = row0 + lr;
            Qs[lc + u][lr] = (gr < SL) ? Q[(long)gr * C3 + k0 + lc + u] : 0.0f;
            int gc = col0 + lr;
            Ks[lc + u][lr] = (gc < SL) ? Kp[(long)gc * C3 + k0 + lc + u] : 0.0f;
        }
        __syncthreads();
        #pragma unroll
        for (int kk = 0; kk < 16; kk++) {
            float a0 = Qs[kk][ty * 2], a1 = Qs[kk][ty * 2 + 1];
            float b0 = Ks[kk][tx * 2], b1 = Ks[kk][tx * 2 + 1];
            acc[0][0] = fmaf(a0, b0, acc[0][0]);
            acc[0][1] = fmaf(a0, b1, acc[0][1]);
            acc[1][0] = fmaf(a1, b0, acc[1][0]);
            acc[1][1] = fmaf(a1, b1, acc[1][1]);
        }
        __syncthreads();
    }
    #pragma unroll
    for (int i = 0; i < 2; i++) {
        int m = row0 + ty * 2 + i;
        if (m >= SL) continue;
        #pragma unroll
        for (int j = 0; j < 2; j++) {
            int n = col0 + tx * 2 + j;
            if (n < SL) S[(long)m * SL + n] = acc[i][j];
        }
    }
}

// ---------------------------------------------------------------------------
// Softmax over rows of length 197, 1/8 scale folded in.
// ---------------------------------------------------------------------------
__global__ void softmax197(float* __restrict__ sc, int nrows)
{
    int row = blockIdx.x * 8 + (threadIdx.x >> 5);
    if (row >= nrows) return;
    int lane = threadIdx.x & 31;
    float* r = sc + (long)row * SL;
    float mx = -1e30f;
    for (int j = lane; j < SL; j += 32) mx = fmaxf(mx, r[j] * 0.125f);
    #pragma unroll
    for (int o = 16; o; o >>= 1) mx = fmaxf(mx, __shfl_xor_sync(0xffffffffu, mx, o));
    float sum = 0.0f;
    for (int j = lane; j < SL; j += 32) {
        float e = expf(r[j] * 0.125f - mx);
        r[j] = e; sum += e;
    }
    #pragma unroll
    for (int o = 16; o; o >>= 1) sum += __shfl_xor_sync(0xffffffffu, sum, o);
    float inv = 1.0f / sum;
    for (int j = lane; j < SL; j += 32) r[j] *= inv;
}

// ---------------------------------------------------------------------------
// Spatial P*V: per z: O = P(197x197) * V(197x64). Tile 32x64x16.
// ---------------------------------------------------------------------------
__global__ void spatial_pv(const float* __restrict__ sc, const float* __restrict__ qkv,
                           float* __restrict__ out)
{
    int z = blockIdx.z, s = z / NH, h = z % NH;
    const float* P = sc + (long)z * SL2;
    const float* V = qkv + (long)s * SL * C3 + 2 * CC + h * HD;
    float* O = out + (long)s * SL * CC + h * HD;
    __shared__ float Ps[16][34], Vs[16][66];
    int tid = threadIdx.x;
    int tx = tid & 15, ty = tid >> 4;
    int row0 = blockIdx.y * 32;
    float acc[2][4] = {};
    int lrp = tid >> 3, lcp = (tid & 7) << 1;
    int lrv = tid >> 4, lcv = (tid & 15) << 2;
    for (int k0 = 0; k0 < SL; k0 += 16) {
        #pragma unroll
        for (int u = 0; u < 2; u++) {
            int gm = row0 + lrp, gk = k0 + lcp + u;
            Ps[lcp + u][lrp] = (gm < SL && gk < SL) ? P[(long)gm * SL + gk] : 0.0f;
        }
        {
            int gk = k0 + lrv;
            #pragma unroll
            for (int u = 0; u < 4; u++)
                Vs[lrv][lcv + u] = (gk < SL) ? V[(long)gk * C3 + lcv + u] : 0.0f;
        }
        __syncthreads();
        #pragma unroll
        for (int kk = 0; kk < 16; kk++) {
            float a0 = Ps[kk][ty * 2], a1 = Ps[kk][ty * 2 + 1];
            float b[4];
            #pragma unroll
            for (int j = 0; j < 4; j++) b[j] = Vs[kk][tx * 4 + j];
            #pragma unroll
            for (int j = 0; j < 4; j++) {
                acc[0][j] = fmaf(a0, b[j], acc[0][j]);
                acc[1][j] = fmaf(a1, b[j], acc[1][j]);
            }
        }
        __syncthreads();
    }
    #pragma unroll
    for (int i = 0; i < 2; i++) {
        int m = row0 + ty * 2 + i;
        if (m >= SL) continue;
        #pragma unroll
        for (int j = 0; j < 4; j++)
            O[(long)m * CC + tx * 4 + j] = acc[i][j];
    }
}

// ---------------------------------------------------------------------------
// Assemble: x_new = concat(init_cls, xt) + concat(cls_out, res_s scatter)
// ---------------------------------------------------------------------------
__global__ void assemble(const float* __restrict__ x, const float* __restrict__ xt,
                         const float* __restrict__ ps, float* __restrict__ out)
{
    int row = blockIdx.x;
    int b = row / NTOK, n = row % NTOK;
    long orow = (long)row * CC;
    if (n == 0) {
        for (int c = threadIdx.x; c < CC; c += 256) {
            float acc = 0.0f;
            #pragma unroll
            for (int t = 0; t < TT; t++)
                acc += ps[((long)(b * TT + t) * SL) * CC + c];
            out[orow + c] = x[orow + c] + acc * 0.125f;
        }
    } else {
        int r = n - 1, hw = r >> 3, t = r & 7;
        long xtrow = ((long)b * 1568 + r) * CC;
        long psrow = ((long)((b * TT + t) * SL + 1 + hw)) * CC;
        for (int c = threadIdx.x; c < CC; c += 256)
            out[orow + c] = xt[xtrow + c] + ps[psrow + c];
    }
}

// ---------------------------------------------------------------------------
// Host launch
// ---------------------------------------------------------------------------
extern "C" void kernel_launch(void* const* d_in, const int* in_sizes, int n_in,
                              void* d_out, int out_size)
{
    const float* x        = (const float*)d_in[0];
    const float* ln_t_g   = (const float*)d_in[1];
    const float* ln_t_b   = (const float*)d_in[2];
    const float* t_qkv_w  = (const float*)d_in[3];
    const float* t_qkv_b  = (const float*)d_in[4];
    const float* t_proj_w = (const float*)d_in[5];
    const float* t_proj_b = (const float*)d_in[6];
    const float* t_fc_w   = (const float*)d_in[7];
    const float* t_fc_b   = (const float*)d_in[8];
    const float* ln1_g    = (const float*)d_in[9];
    const float* ln1_b    = (const float*)d_in[10];
    const float* s_qkv_w  = (const float*)d_in[11];
    const float* s_qkv_b  = (const float*)d_in[12];
    const float* s_proj_w = (const float*)d_in[13];
    const float* s_proj_b = (const float*)d_in[14];
    const float* ln2_g    = (const float*)d_in[15];
    const float* ln2_b    = (const float*)d_in[16];
    const float* fc1_w    = (const float*)d_in[17];
    const float* fc1_b    = (const float*)d_in[18];
    const float* fc2_w    = (const float*)d_in[19];
    const float* fc2_b    = (const float*)d_in[20];
    float* out = (float*)d_out;

    float *ln, *qkv, *attn, *proj, *xt, *sc, *fc1;
    cudaGetSymbolAddress((void**)&ln,   g_ln);
    cudaGetSymbolAddress((void**)&qkv,  g_qkv);
    cudaGetSymbolAddress((void**)&attn, g_attn);
    cudaGetSymbolAddress((void**)&proj, g_proj);
    cudaGetSymbolAddress((void**)&xt,   g_xt);
    cudaGetSymbolAddress((void**)&sc,   g_sc);
    cudaGetSymbolAddress((void**)&fc1,  g_fc1);

    // 1. temporal LN (skip cls)
    ln_kernel<<<MT, 256>>>(x, nullptr, ln_t_g, ln_t_b, ln, 0);

    // 2. temporal qkv: 6272 x 2304 x 768
    {
        dim3 g(C3 / 128, (MT + 127) / 128);
        gemm_nt<0><<<g, 256>>>(ln, CC, t_qkv_w, CC, t_qkv_b, qkv, C3, nullptr, MT, C3, CC);
    }

    // 3. temporal attention
    temporal_attn<<<dim3(BB * HW, NH), 64>>>(qkv, attn);

    // 4. temporal proj: 6272 x 768 x 768
    {
        dim3 g(CC / 128, (MT + 127) / 128);
        gemm_nt<0><<<g, 256>>>(attn, CC, t_proj_w, CC, t_proj_b, proj, CC, nullptr, MT, CC, CC);
    }

    // 5. t_fc + residual from x (skip-cls)
    {
        dim3 g(CC / 128, (MT + 127) / 128);
        gemm_nt<2><<<g, 256>>>(proj, CC, t_fc_w, CC, t_fc_b, xt, CC, x, MT, CC, CC);
    }

    // 6. spatial gather + LN1
    ln_kernel<<<MS, 256>>>(x, xt, ln1_g, ln1_b, ln, 1);

    // 7. spatial qkv: 6304 x 2304 x 768
    {
        dim3 g(C3 / 128, (MS + 127) / 128);
        gemm_nt<0><<<g, 256>>>(ln, CC, s_qkv_w, CC, s_qkv_b, qkv, C3, nullptr, MS, C3, CC);
    }

    // 8-10. spatial attention
    spatial_scores<<<dim3(7, 7, ZB), 256>>>(qkv, sc);
    softmax197<<<(ZB * SL + 7) / 8, 256>>>(sc, ZB * SL);
    spatial_pv<<<dim3(1, 7, ZB), 256>>>(sc, qkv, attn);

    // 11. spatial proj: 6304 x 768 x 768
    {
        dim3 g(CC / 128, (MS + 127) / 128);
        gemm_nt<0><<<g, 256>>>(attn, CC, s_proj_w, CC, s_proj_b, proj, CC, nullptr, MS, CC, CC);
    }

    // 12. assemble x_new into d_out
    assemble<<<MX, 256>>>(x, xt, proj, out);

    // 13. LN2
    ln_kernel<<<MX, 256>>>(out, nullptr, ln2_g, ln2_b, ln, 2);

    // 14. fc1 + gelu: 6276 x 3072 x 768
    {
        dim3 g(HIDDEN / 128, (MX + 127) / 128);
        gemm_nt<1><<<g, 256>>>(ln, CC, fc1_w, CC, fc1_b, fc1, HIDDEN, nullptr, MX, HIDDEN, CC);
    }

    // 15. fc2 + in-place residual
    {
        dim3 g(CC / 128, (MX + 127) / 128);
        gemm_nt<3><<<g, 256>>>(fc1, HIDDEN, fc2_w, HIDDEN, fc2_b, out, CC, nullptr, MX, CC, HIDDEN);
    }
}

// round 4
// speedup vs baseline: 3.4528x; 1.9471x over previous
#include <cuda_runtime.h>
#include <cuda_bf16.h>
#include <math.h>
#include <stdint.h>

// ---------------------------------------------------------------------------
// Problem constants
// ---------------------------------------------------------------------------
#define CC     768
#define C3     2304
#define NH     12
#define HD     64
#define HIDDEN 3072
#define TT     8
#define HW     196
#define BB     4
#define NTOK   1569
#define MT     6272
#define MS     6304
#define MX     6276
#define SL     197
#define SB     32
#define ZB     (SB*NH)
#define SL2    (SL*SL)

// ---------------------------------------------------------------------------
// Static device scratch
// ---------------------------------------------------------------------------
__device__ float g_qkv [(size_t)MS * C3];      // fp32 qkv (attention input)
__device__ float g_xt  [(size_t)MT * CC];      // fp32 xt
__device__ float g_sc  [(size_t)ZB * SL2];     // fp32 attention scores
__device__ float g_proj[(size_t)MS * CC];      // fp32 spatial proj out

__device__ __nv_bfloat16 g_ln_h[(size_t)MS * CC];
__device__ __nv_bfloat16 g_ln_l[(size_t)MS * CC];
__device__ __nv_bfloat16 g_at_h[(size_t)MS * CC];
__device__ __nv_bfloat16 g_at_l[(size_t)MS * CC];
__device__ __nv_bfloat16 g_pj_h[(size_t)MT * CC];
__device__ __nv_bfloat16 g_pj_l[(size_t)MT * CC];
__device__ __nv_bfloat16 g_f1_h[(size_t)MX * HIDDEN];
__device__ __nv_bfloat16 g_f1_l[(size_t)MX * HIDDEN];
__device__ __nv_bfloat16 g_w_h [(size_t)HIDDEN * CC];
__device__ __nv_bfloat16 g_w_l [(size_t)HIDDEN * CC];

// ---------------------------------------------------------------------------
// Helpers
// ---------------------------------------------------------------------------
__device__ __forceinline__ float gelu_exact(float v) {
    return 0.5f * v * (1.0f + erff(v * 0.7071067811865475f));
}

__device__ __forceinline__ void f2hl(float x, __nv_bfloat16& h, __nv_bfloat16& l) {
    h = __float2bfloat16(x);
    l = __float2bfloat16(x - __bfloat162float(h));
}

__device__ __forceinline__ uint32_t smem_u32(const void* p) {
    uint32_t a;
    asm("{ .reg .u64 t; cvta.to.shared.u64 t, %1; cvt.u32.u64 %0, t; }" : "=r"(a) : "l"(p));
    return a;
}

__device__ __forceinline__ void cpasync16(uint32_t dst, const void* src) {
    asm volatile("cp.async.cg.shared.global [%0], [%1], 16;" :: "r"(dst), "l"(src));
}
#define CP_COMMIT() asm volatile("cp.async.commit_group;" ::: "memory")
#define CP_WAIT0()  asm volatile("cp.async.wait_group 0;" ::: "memory")

__device__ __forceinline__ void ldm4(uint32_t* r, uint32_t addr) {
    asm volatile("ldmatrix.sync.aligned.m8n8.x4.shared.b16 {%0,%1,%2,%3}, [%4];"
                 : "=r"(r[0]), "=r"(r[1]), "=r"(r[2]), "=r"(r[3]) : "r"(addr));
}

__device__ __forceinline__ void mma16816(float* d, const uint32_t* a, const uint32_t* b) {
    asm volatile(
        "mma.sync.aligned.m16n8k16.row.col.f32.bf16.bf16.f32 "
        "{%0,%1,%2,%3}, {%4,%5,%6,%7}, {%8,%9}, {%0,%1,%2,%3};"
        : "+f"(d[0]), "+f"(d[1]), "+f"(d[2]), "+f"(d[3])
        : "r"(a[0]), "r"(a[1]), "r"(a[2]), "r"(a[3]), "r"(b[0]), "r"(b[1]));
}

// ---------------------------------------------------------------------------
// Split-bf16 HMMA NT GEMM:
//   C[M,N] = A[M,K]*B[N,K]^T + bias (+epilogue)
//   fp32-accurate via Ah*Bh + Ah*Bl + Al*Bh (3 mma chains, fp32 accum).
// Inputs: separate hi/lo bf16 arrays, K-major. N%128==0, K%32==0.
// CTA tile 128x128, k-step 32, 8 warps (each 64Mx32N), 2-stage cp.async.
//   EPI 0: +bias   1: gelu(+bias)   2: +bias+resid(skip-cls)   3: +bias+C
//   OUT 0: fp32 C  1: hi/lo bf16 arrays (Ch, Cl)
// smem: 2 buffers x {Ah,Al,Bh,Bl} x 128 rows x 80B = 81920 bytes.
// ---------------------------------------------------------------------------
#define BUFSZ  40960u
#define OFF_AH 0u
#define OFF_AL 10240u
#define OFF_BH 20480u
#define OFF_BL 30720u
#define GEMM_SMEM (2 * BUFSZ)

template<int EPI, int OUT>
__global__ void __launch_bounds__(256)
gemm_mma(const __nv_bfloat16* __restrict__ Ahg, const __nv_bfloat16* __restrict__ Alg,
         const __nv_bfloat16* __restrict__ Bhg, const __nv_bfloat16* __restrict__ Blg,
         const float* __restrict__ bias,
         float* __restrict__ C,
         __nv_bfloat16* __restrict__ Ch, __nv_bfloat16* __restrict__ Cl,
         const float* __restrict__ resid,
         int M, int N, int K)
{
    extern __shared__ char smem[];
    const uint32_t sb = smem_u32(smem);

    const int tid  = threadIdx.x;
    const int wid  = tid >> 5;
    const int lane = tid & 31;
    const int row0 = blockIdx.y * 128;
    const int col0 = blockIdx.x * 128;
    const int KT   = K >> 5;

    // loader mapping
    const int lrow = (tid & 255) >> 2;  // placeholder; real mapping below

    float acc[4][4][4];
    #pragma unroll
    for (int a = 0; a < 4; a++)
        #pragma unroll
        for (int b = 0; b < 4; b++)
            #pragma unroll
            for (int c = 0; c < 4; c++) acc[a][b][c] = 0.0f;

    // ---- stage loader (cp.async) ----
    auto load_stage = [&](int kt, int buf) {
        const int kw = kt * 32;
        const uint32_t dstb = sb + buf * BUFSZ;
        #pragma unroll
        for (int q = 0; q < 4; q++) {            // A: hi (q<2), lo (q>=2)
            int cid = q * 256 + tid;             // 0..1023
            int arr = cid >> 9;
            int idx = cid & 511;
            int row = idx >> 2, ch = idx & 3;
            int ar  = min(row0 + row, M - 1);
            const __nv_bfloat16* src = (arr ? Alg : Ahg) + (size_t)ar * K + kw + ch * 8;
            cpasync16(dstb + (arr ? OFF_AL : OFF_AH) + row * 80u + ch * 16u, src);
        }
        #pragma unroll
        for (int q = 0; q < 4; q++) {            // B
            int cid = q * 256 + tid;
            int arr = cid >> 9;
            int idx = cid & 511;
            int row = idx >> 2, ch = idx & 3;
            const __nv_bfloat16* src = (arr ? Blg : Bhg) + (size_t)(col0 + row) * K + kw + ch * 8;
            cpasync16(dstb + (arr ? OFF_BL : OFF_BH) + row * 80u + ch * 16u, src);
        }
        CP_COMMIT();
    };

    load_stage(0, 0);
    CP_WAIT0();
    __syncthreads();

    const int m0w = (wid & 1) * 64;
    const int n0w = (wid >> 1) * 32;
    const uint32_t a_off = (uint32_t)(m0w + (lane & 15)) * 80u + (uint32_t)((lane >> 4) << 4);
    const uint32_t b_off = (uint32_t)(n0w + (lane & 7) + ((lane >> 4) << 3)) * 80u
                         + (uint32_t)(((lane >> 3) & 1) << 4);

    for (int kt = 0; kt < KT; kt++) {
        const int buf = kt & 1;
        if (kt + 1 < KT) load_stage(kt + 1, buf ^ 1);

        const uint32_t bb = sb + buf * BUFSZ;
        #pragma unroll
        for (int s = 0; s < 2; s++) {
            uint32_t ah[4][4], al[4][4], bh[4][2], bl[4][2];
            #pragma unroll
            for (int mi = 0; mi < 4; mi++) {
                ldm4(ah[mi], bb + OFF_AH + a_off + mi * 1280u + s * 32u);
                ldm4(al[mi], bb + OFF_AL + a_off + mi * 1280u + s * 32u);
            }
            #pragma unroll
            for (int nj = 0; nj < 2; nj++) {
                uint32_t t[4];
                ldm4(t, bb + OFF_BH + b_off + nj * 1280u + s * 32u);
                bh[nj*2][0] = t[0]; bh[nj*2][1] = t[1];
                bh[nj*2+1][0] = t[2]; bh[nj*2+1][1] = t[3];
                ldm4(t, bb + OFF_BL + b_off + nj * 1280u + s * 32u);
                bl[nj*2][0] = t[0]; bl[nj*2][1] = t[1];
                bl[nj*2+1][0] = t[2]; bl[nj*2+1][1] = t[3];
            }
            #pragma unroll
            for (int mi = 0; mi < 4; mi++)
                #pragma unroll
                for (int nj = 0; nj < 4; nj++) {
                    mma16816(acc[mi][nj], ah[mi], bh[nj]);
                    mma16816(acc[mi][nj], ah[mi], bl[nj]);
                    mma16816(acc[mi][nj], al[mi], bh[nj]);
                }
        }
        CP_WAIT0();
        __syncthreads();
    }

    // ---- epilogue ----
    #pragma unroll
    for (int mi = 0; mi < 4; mi++) {
        const int rbase = row0 + m0w + mi * 16 + (lane >> 2);
        #pragma unroll
        for (int half = 0; half < 2; half++) {
            const int m = rbase + half * 8;
            if (m >= M) continue;
            #pragma unroll
            for (int nj = 0; nj < 4; nj++) {
                const int n = col0 + n0w + nj * 8 + (lane & 3) * 2;
                float v0 = acc[mi][nj][half * 2 + 0] + bias[n];
                float v1 = acc[mi][nj][half * 2 + 1] + bias[n + 1];
                if (EPI == 1) { v0 = gelu_exact(v0); v1 = gelu_exact(v1); }
                if (EPI == 2) {
                    const float* rs = resid + (size_t)(m + m / 1568 + 1) * CC + n;
                    v0 += rs[0]; v1 += rs[1];
                }
                if (OUT == 0) {
                    float* cp = C + (size_t)m * N + n;
                    if (EPI == 3) {
                        float2 old = *(const float2*)cp;
                        v0 += old.x; v1 += old.y;
                    }
                    float2 o = {v0, v1};
                    *(float2*)cp = o;
                } else {
                    __nv_bfloat16 h0, l0, h1, l1;
                    f2hl(v0, h0, l0);
                    f2hl(v1, h1, l1);
                    *(__nv_bfloat162*)(Ch + (size_t)m * N + n) = __halves2bfloat162(h0, h1);
                    *(__nv_bfloat162*)(Cl + (size_t)m * N + n) = __halves2bfloat162(l0, l1);
                }
            }
        }
    }
    (void)lrow;
}

// ---------------------------------------------------------------------------
// Weight conversion: fp32 -> hi/lo bf16 arrays
// ---------------------------------------------------------------------------
__global__ void conv_hl(const float4* __restrict__ in,
                        __nv_bfloat162* __restrict__ oh,
                        __nv_bfloat162* __restrict__ ol, int n4)
{
    int i = blockIdx.x * blockDim.x + threadIdx.x;
    if (i < n4) {
        float4 v = in[i];
        __nv_bfloat16 h0, l0, h1, l1, h2, l2, h3, l3;
        f2hl(v.x, h0, l0); f2hl(v.y, h1, l1);
        f2hl(v.z, h2, l2); f2hl(v.w, h3, l3);
        oh[i * 2 + 0] = __halves2bfloat162(h0, h1);
        oh[i * 2 + 1] = __halves2bfloat162(h2, h3);
        ol[i * 2 + 0] = __halves2bfloat162(l0, l1);
        ol[i * 2 + 1] = __halves2bfloat162(l2, l3);
    }
}

// ---------------------------------------------------------------------------
// LayerNorm over 768 (=256*3). One block/row. Writes hi/lo bf16.
// ---------------------------------------------------------------------------
__global__ void ln_kernel(const float* __restrict__ src0,
                          const float* __restrict__ xt,
                          const float* __restrict__ g,
                          const float* __restrict__ bta,
                          __nv_bfloat16* __restrict__ oh,
                          __nv_bfloat16* __restrict__ ol, int mode)
{
    int m = blockIdx.x;
    const float* src;
    if (mode == 0) {
        src = src0 + (size_t)(m + m / 1568 + 1) * CC;
    } else if (mode == 1) {
        int sb = m / SL, p = m % SL;
        int b = sb >> 3, t = sb & 7;
        if (p == 0) src = src0 + (size_t)b * NTOK * CC;
        else        src = xt + ((size_t)(b * HW + (p - 1)) * TT + t) * CC;
    } else {
        src = src0 + (size_t)m * CC;
    }
    int tid = threadIdx.x;
    float v0 = src[tid], v1 = src[tid + 256], v2 = src[tid + 512];
    float s = v0 + v1 + v2;
    __shared__ float sh[32];
    int lane = tid & 31, wid = tid >> 5;
    #pragma unroll
    for (int o = 16; o; o >>= 1) s += __shfl_xor_sync(0xffffffffu, s, o);
    if (lane == 0) sh[wid] = s;
    __syncthreads();
    if (wid == 0) {
        float t2 = (lane < 8) ? sh[lane] : 0.0f;
        #pragma unroll
        for (int o = 4; o; o >>= 1) t2 += __shfl_xor_sync(0xffffffffu, t2, o);
        if (lane == 0) sh[0] = t2;
    }
    __syncthreads();
    float mean = sh[0] * (1.0f / 768.0f);
    __syncthreads();
    float d0 = v0 - mean, d1 = v1 - mean, d2 = v2 - mean;
    float s2 = d0 * d0 + d1 * d1 + d2 * d2;
    #pragma unroll
    for (int o = 16; o; o >>= 1) s2 += __shfl_xor_sync(0xffffffffu, s2, o);
    if (lane == 0) sh[wid] = s2;
    __syncthreads();
    if (wid == 0) {
        float t2 = (lane < 8) ? sh[lane] : 0.0f;
        #pragma unroll
        for (int o = 4; o; o >>= 1) t2 += __shfl_xor_sync(0xffffffffu, t2, o);
        if (lane == 0) sh[0] = t2;
    }
    __syncthreads();
    float inv = rsqrtf(sh[0] * (1.0f / 768.0f) + 1e-5f);
    size_t ob = (size_t)m * CC;
    #pragma unroll
    for (int p = 0; p < 3; p++) {
        float d = (p == 0) ? d0 : (p == 1) ? d1 : d2;
        int c = tid + p * 256;
        float v = d * inv * g[c] + bta[c];
        __nv_bfloat16 h, l;
        f2hl(v, h, l);
        oh[ob + c] = h;
        ol[ob + c] = l;
    }
}

// ---------------------------------------------------------------------------
// Temporal attention: fused per (seq, head). Writes hi/lo bf16.
// ---------------------------------------------------------------------------
__global__ void temporal_attn(const float* __restrict__ qkv,
                              __nv_bfloat16* __restrict__ oh,
                              __nv_bfloat16* __restrict__ ol)
{
    int seq = blockIdx.x, h = blockIdx.y;
    __shared__ float q[TT][HD], k[TT][HD], v[TT][HD], p[TT][TT];
    int tid = threadIdx.x;
    size_t base = (size_t)(seq * TT) * C3 + h * HD;
    #pragma unroll
    for (int t = 0; t < TT; t++) {
        q[t][tid] = qkv[base + (size_t)t * C3 + tid];
        k[t][tid] = qkv[base + (size_t)t * C3 + CC + tid];
        v[t][tid] = qkv[base + (size_t)t * C3 + 2 * CC + tid];
    }
    __syncthreads();
    int i = tid >> 3, j = tid & 7;
    float s = 0.0f;
    #pragma unroll
    for (int d = 0; d < HD; d++) s = fmaf(q[i][d], k[j][d], s);
    p[i][j] = s * 0.125f;
    __syncthreads();
    if (tid < TT) {
        float mx = -1e30f;
        #pragma unroll
        for (int jj = 0; jj < TT; jj++) mx = fmaxf(mx, p[tid][jj]);
        float sum = 0.0f;
        #pragma unroll
        for (int jj = 0; jj < TT; jj++) {
            float e = expf(p[tid][jj] - mx);
            p[tid][jj] = e; sum += e;
        }
        float invs = 1.0f / sum;
        #pragma unroll
        for (int jj = 0; jj < TT; jj++) p[tid][jj] *= invs;
    }
    __syncthreads();
    #pragma unroll
    for (int t = 0; t < TT; t++) {
        float o = 0.0f;
        #pragma unroll
        for (int jj = 0; jj < TT; jj++) o = fmaf(p[t][jj], v[jj][tid], o);
        __nv_bfloat16 hh, ll;
        f2hl(o, hh, ll);
        size_t oi = (size_t)(seq * TT + t) * CC + h * HD + tid;
        oh[oi] = hh;
        ol[oi] = ll;
    }
}

// ---------------------------------------------------------------------------
// Spatial scores: per z=(s,h): S = Q * K^T, 197x197x64.
// ---------------------------------------------------------------------------
__global__ void spatial_scores(const float* __restrict__ qkv, float* __restrict__ sc)
{
    int z = blockIdx.z, s = z / NH, h = z % NH;
    const float* Q  = qkv + (size_t)s * SL * C3 + h * HD;
    const float* Kp = Q + CC;
    float* S = sc + (size_t)z * SL2;
    __shared__ float Qs[16][34], Ks[16][34];
    int tid = threadIdx.x;
    int tx = tid & 15, ty = tid >> 4;
    int row0 = blockIdx.y * 32, col0 = blockIdx.x * 32;
    float acc[2][2] = {};
    int lr = tid >> 3;
    int lc = (tid & 7) << 1;
    for (int k0 = 0; k0 < HD; k0 += 16) {
        #pragma unroll
        for (int u = 0; u < 2; u++) {
            int gr = row0 + lr;
            Qs[lc + u][lr] = (gr < SL) ? Q[(size_t)gr * C3 + k0 + lc + u] : 0.0f;
            int gc = col0 + lr;
            Ks[lc + u][lr] = (gc < SL) ? Kp[(size_t)gc * C3 + k0 + lc + u] : 0.0f;
        }
        __syncthreads();
        #pragma unroll
        for (int kk = 0; kk < 16; kk++) {
            float a0 = Qs[kk][ty * 2], a1 = Qs[kk][ty * 2 + 1];
            float b0 = Ks[kk][tx * 2], b1 = Ks[kk][tx * 2 + 1];
            acc[0][0] = fmaf(a0, b0, acc[0][0]);
            acc[0][1] = fmaf(a0, b1, acc[0][1]);
            acc[1][0] = fmaf(a1, b0, acc[1][0]);
            acc[1][1] = fmaf(a1, b1, acc[1][1]);
        }
        __syncthreads();
    }
    #pragma unroll
    for (int i = 0; i < 2; i++) {
        int m = row0 + ty * 2 + i;
        if (m >= SL) continue;
        #pragma unroll
        for (int j = 0; j < 2; j++) {
            int n = col0 + tx * 2 + j;
            if (n < SL) S[(size_t)m * SL + n] = acc[i][j];
        }
    }
}

// ---------------------------------------------------------------------------
// Softmax over rows of length 197 (1/8 scale folded in).
// ---------------------------------------------------------------------------
__global__ void softmax197(float* __restrict__ sc, int nrows)
{
    int row = blockIdx.x * 8 + (threadIdx.x >> 5);
    if (row >= nrows) return;
    int lane = threadIdx.x & 31;
    float* r = sc + (size_t)row * SL;
    float mx = -1e30f;
    for (int j = lane; j < SL; j += 32) mx = fmaxf(mx, r[j] * 0.125f);
    #pragma unroll
    for (int o = 16; o; o >>= 1) mx = fmaxf(mx, __shfl_xor_sync(0xffffffffu, mx, o));
    float sum = 0.0f;
    for (int j = lane; j < SL; j += 32) {
        float e = expf(r[j] * 0.125f - mx);
        r[j] = e; sum += e;
    }
    #pragma unroll
    for (int o = 16; o; o >>= 1) sum += __shfl_xor_sync(0xffffffffu, sum, o);
    float inv = 1.0f / sum;
    for (int j = lane; j < SL; j += 32) r[j] *= inv;
}

// ---------------------------------------------------------------------------
// Spatial P*V: per z: O = P(197x197) * V(197x64). Writes hi/lo bf16.
// ---------------------------------------------------------------------------
__global__ void spatial_pv(const float* __restrict__ sc, const float* __restrict__ qkv,
                           __nv_bfloat16* __restrict__ oh, __nv_bfloat16* __restrict__ ol)
{
    int z = blockIdx.z, s = z / NH, h = z % NH;
    const float* P = sc + (size_t)z * SL2;
    const float* V = qkv + (size_t)s * SL * C3 + 2 * CC + h * HD;
    size_t obase = (size_t)s * SL * CC + h * HD;
    __shared__ float Ps[16][34], Vs[16][66];
    int tid = threadIdx.x;
    int tx = tid & 15, ty = tid >> 4;
    int row0 = blockIdx.y * 32;
    float acc[2][4] = {};
    int lrp = tid >> 3, lcp = (tid & 7) << 1;
    int lrv = tid >> 4, lcv = (tid & 15) << 2;
    for (int k0 = 0; k0 < SL; k0 += 16) {
        #pragma unroll
        for (int u = 0; u < 2; u++) {
            int gm = row0 + lrp, gk = k0 + lcp + u;
            Ps[lcp + u][lrp] = (gm < SL && gk < SL) ? P[(size_t)gm * SL + gk] : 0.0f;
        }
        {
            int gk = k0 + lrv;
            #pragma unroll
            for (int u = 0; u < 4; u++)
                Vs[lrv][lcv + u] = (gk < SL) ? V[(size_t)gk * C3 + lcv + u] : 0.0f;
        }
        __syncthreads();
        #pragma unroll
        for (int kk = 0; kk < 16; kk++) {
            float a0 = Ps[kk][ty * 2], a1 = Ps[kk][ty * 2 + 1];
            float b[4];
            #pragma unroll
            for (int j = 0; j < 4; j++) b[j] = Vs[kk][tx * 4 + j];
            #pragma unroll
            for (int j = 0; j < 4; j++) {
                acc[0][j] = fmaf(a0, b[j], acc[0][j]);
                acc[1][j] = fmaf(a1, b[j], acc[1][j]);
            }
        }
        __syncthreads();
    }
    #pragma unroll
    for (int i = 0; i < 2; i++) {
        int m = row0 + ty * 2 + i;
        if (m >= SL) continue;
        #pragma unroll
        for (int j = 0; j < 4; j++) {
            __nv_bfloat16 hh, ll;
            f2hl(acc[i][j], hh, ll);
            size_t oi = obase + (size_t)m * CC + tx * 4 + j;
            oh[oi] = hh;
            ol[oi] = ll;
        }
    }
}

// ---------------------------------------------------------------------------
// Assemble x_new into d_out
// ---------------------------------------------------------------------------
__global__ void assemble(const float* __restrict__ x, const float* __restrict__ xt,
                         const float* __restrict__ ps, float* __restrict__ out)
{
    int row = blockIdx.x;
    int b = row / NTOK, n = row % NTOK;
    size_t orow = (size_t)row * CC;
    if (n == 0) {
        for (int c = threadIdx.x; c < CC; c += 256) {
            float acc = 0.0f;
            #pragma unroll
            for (int t = 0; t < TT; t++)
                acc += ps[((size_t)(b * TT + t) * SL) * CC + c];
            out[orow + c] = x[orow + c] + acc * 0.125f;
        }
    } else {
        int r = n - 1, hw = r >> 3, t = r & 7;
        size_t xtrow = ((size_t)b * 1568 + r) * CC;
        size_t psrow = ((size_t)((b * TT + t) * SL + 1 + hw)) * CC;
        for (int c = threadIdx.x; c < CC; c += 256)
            out[orow + c] = xt[xtrow + c] + ps[psrow + c];
    }
}

// ---------------------------------------------------------------------------
// Host launch
// ---------------------------------------------------------------------------
static void conv_w(const float* w, __nv_bfloat16* wh, __nv_bfloat16* wl, int elems) {
    int n4 = elems / 4;
    conv_hl<<<(n4 + 255) / 256, 256>>>((const float4*)w, (__nv_bfloat162*)wh,
                                       (__nv_bfloat162*)wl, n4);
}

extern "C" void kernel_launch(void* const* d_in, const int* in_sizes, int n_in,
                              void* d_out, int out_size)
{
    const float* x        = (const float*)d_in[0];
    const float* ln_t_g   = (const float*)d_in[1];
    const float* ln_t_b   = (const float*)d_in[2];
    const float* t_qkv_w  = (const float*)d_in[3];
    const float* t_qkv_b  = (const float*)d_in[4];
    const float* t_proj_w = (const float*)d_in[5];
    const float* t_proj_b = (const float*)d_in[6];
    const float* t_fc_w   = (const float*)d_in[7];
    const float* t_fc_b   = (const float*)d_in[8];
    const float* ln1_g    = (const float*)d_in[9];
    const float* ln1_b    = (const float*)d_in[10];
    const float* s_qkv_w  = (const float*)d_in[11];
    const float* s_qkv_b  = (const float*)d_in[12];
    const float* s_proj_w = (const float*)d_in[13];
    const float* s_proj_b = (const float*)d_in[14];
    const float* ln2_g    = (const float*)d_in[15];
    const float* ln2_b    = (const float*)d_in[16];
    const float* fc1_w    = (const float*)d_in[17];
    const float* fc1_b    = (const float*)d_in[18];
    const float* fc2_w    = (const float*)d_in[19];
    const float* fc2_b    = (const float*)d_in[20];
    float* out = (float*)d_out;

    float *qkv, *xt, *sc, *proj;
    __nv_bfloat16 *lnh, *lnl, *ath, *atl, *pjh, *pjl, *f1h, *f1l, *wh, *wl;
    cudaGetSymbolAddress((void**)&qkv,  g_qkv);
    cudaGetSymbolAddress((void**)&xt,   g_xt);
    cudaGetSymbolAddress((void**)&sc,   g_sc);
    cudaGetSymbolAddress((void**)&proj, g_proj);
    cudaGetSymbolAddress((void**)&lnh,  g_ln_h);
    cudaGetSymbolAddress((void**)&lnl,  g_ln_l);
    cudaGetSymbolAddress((void**)&ath,  g_at_h);
    cudaGetSymbolAddress((void**)&atl,  g_at_l);
    cudaGetSymbolAddress((void**)&pjh,  g_pj_h);
    cudaGetSymbolAddress((void**)&pjl,  g_pj_l);
    cudaGetSymbolAddress((void**)&f1h,  g_f1_h);
    cudaGetSymbolAddress((void**)&f1l,  g_f1_l);
    cudaGetSymbolAddress((void**)&wh,   g_w_h);
    cudaGetSymbolAddress((void**)&wl,   g_w_l);

    cudaFuncSetAttribute(gemm_mma<0,0>, cudaFuncAttributeMaxDynamicSharedMemorySize, GEMM_SMEM);
    cudaFuncSetAttribute(gemm_mma<0,1>, cudaFuncAttributeMaxDynamicSharedMemorySize, GEMM_SMEM);
    cudaFuncSetAttribute(gemm_mma<1,1>, cudaFuncAttributeMaxDynamicSharedMemorySize, GEMM_SMEM);
    cudaFuncSetAttribute(gemm_mma<2,0>, cudaFuncAttributeMaxDynamicSharedMemorySize, GEMM_SMEM);
    cudaFuncSetAttribute(gemm_mma<3,0>, cudaFuncAttributeMaxDynamicSharedMemorySize, GEMM_SMEM);

    // 1. temporal LN (skip cls) -> hi/lo
    ln_kernel<<<MT, 256>>>(x, nullptr, ln_t_g, ln_t_b, lnh, lnl, 0);

    // 2. temporal qkv -> fp32
    conv_w(t_qkv_w, wh, wl, C3 * CC);
    gemm_mma<0,0><<<dim3(C3/128, (MT+127)/128), 256, GEMM_SMEM>>>(
        lnh, lnl, wh, wl, t_qkv_b, qkv, nullptr, nullptr, nullptr, MT, C3, CC);

    // 3. temporal attention -> hi/lo
    temporal_attn<<<dim3(BB * HW, NH), 64>>>(qkv, ath, atl);

    // 4. temporal proj -> hi/lo
    conv_w(t_proj_w, wh, wl, CC * CC);
    gemm_mma<0,1><<<dim3(CC/128, (MT+127)/128), 256, GEMM_SMEM>>>(
        ath, atl, wh, wl, t_proj_b, nullptr, pjh, pjl, nullptr, MT, CC, CC);

    // 5. t_fc + residual from x (skip-cls) -> fp32 xt
    conv_w(t_fc_w, wh, wl, CC * CC);
    gemm_mma<2,0><<<dim3(CC/128, (MT+127)/128), 256, GEMM_SMEM>>>(
        pjh, pjl, wh, wl, t_fc_b, xt, nullptr, nullptr, x, MT, CC, CC);

    // 6. spatial gather + LN1 -> hi/lo
    ln_kernel<<<MS, 256>>>(x, xt, ln1_g, ln1_b, lnh, lnl, 1);

    // 7. spatial qkv -> fp32
    conv_w(s_qkv_w, wh, wl, C3 * CC);
    gemm_mma<0,0><<<dim3(C3/128, (MS+127)/128), 256, GEMM_SMEM>>>(
        lnh, lnl, wh, wl, s_qkv_b, qkv, nullptr, nullptr, nullptr, MS, C3, CC);

    // 8-10. spatial attention -> hi/lo
    spatial_scores<<<dim3(7, 7, ZB), 256>>>(qkv, sc);
    softmax197<<<(ZB * SL + 7) / 8, 256>>>(sc, ZB * SL);
    spatial_pv<<<dim3(1, 7, ZB), 256>>>(sc, qkv, ath, atl);

    // 11. spatial proj -> fp32
    conv_w(s_proj_w, wh, wl, CC * CC);
    gemm_mma<0,0><<<dim3(CC/128, (MS+127)/128), 256, GEMM_SMEM>>>(
        ath, atl, wh, wl, s_proj_b, proj, nullptr, nullptr, nullptr, MS, CC, CC);

    // 12. assemble x_new into d_out
    assemble<<<MX, 256>>>(x, xt, proj, out);

    // 13. LN2 -> hi/lo
    ln_kernel<<<MX, 256>>>(out, nullptr, ln2_g, ln2_b, lnh, lnl, 2);

    // 14. fc1 + gelu -> hi/lo
    conv_w(fc1_w, wh, wl, HIDDEN * CC);
    gemm_mma<1,1><<<dim3(HIDDEN/128, (MX+127)/128), 256, GEMM_SMEM>>>(
        lnh, lnl, wh, wl, fc1_b, nullptr, f1h, f1l, nullptr, MX, HIDDEN, CC);

    // 15. fc2 + in-place residual on d_out
    conv_w(fc2_w, wh, wl, CC * HIDDEN);
    gemm_mma<3,0><<<dim3(CC/128, (MX+127)/128), 256, GEMM_SMEM>>>(
        f1h, f1l, wh, wl, fc2_b, out, nullptr, nullptr, nullptr, MX, CC, HIDDEN);
}

// round 5
// speedup vs baseline: 3.7248x; 1.0788x over previous
#include <cuda_runtime.h>
#include <cuda_bf16.h>
#include <math.h>
#include <stdint.h>

// ---------------------------------------------------------------------------
// Problem constants
// ---------------------------------------------------------------------------
#define CC     768
#define C3     2304
#define NH     12
#define HD     64
#define HIDDEN 3072
#define TT     8
#define HW     196
#define BB     4
#define NTOK   1569
#define MT     6272
#define MS     6304
#define MX     6276
#define SL     197
#define SB     32
#define ZB     (SB*NH)
#define SL2    (SL*SL)

// ---------------------------------------------------------------------------
// Static device scratch
// ---------------------------------------------------------------------------
__device__ float g_qkv [(size_t)MS * C3];      // fp32 qkv (attention input)
__device__ float g_xt  [(size_t)MT * CC];      // fp32 xt
__device__ float g_sc  [(size_t)ZB * SL2];     // fp32 attention scores
__device__ float g_proj[(size_t)MS * CC];      // fp32 spatial proj out

__device__ __nv_bfloat16 g_ln_h[(size_t)MS * CC];
__device__ __nv_bfloat16 g_ln_l[(size_t)MS * CC];
__device__ __nv_bfloat16 g_at_h[(size_t)MS * CC];
__device__ __nv_bfloat16 g_at_l[(size_t)MS * CC];
__device__ __nv_bfloat16 g_pj_h[(size_t)MT * CC];
__device__ __nv_bfloat16 g_pj_l[(size_t)MT * CC];
__device__ __nv_bfloat16 g_f1_h[(size_t)MX * HIDDEN];
__device__ __nv_bfloat16 g_f1_l[(size_t)MX * HIDDEN];

// dedicated converted-weight buffers (hi/lo)
__device__ __nv_bfloat16 g_wtq_h[(size_t)C3 * CC],     g_wtq_l[(size_t)C3 * CC];
__device__ __nv_bfloat16 g_wtp_h[(size_t)CC * CC],     g_wtp_l[(size_t)CC * CC];
__device__ __nv_bfloat16 g_wtf_h[(size_t)CC * CC],     g_wtf_l[(size_t)CC * CC];
__device__ __nv_bfloat16 g_wsq_h[(size_t)C3 * CC],     g_wsq_l[(size_t)C3 * CC];
__device__ __nv_bfloat16 g_wsp_h[(size_t)CC * CC],     g_wsp_l[(size_t)CC * CC];
__device__ __nv_bfloat16 g_wf1_h[(size_t)HIDDEN * CC], g_wf1_l[(size_t)HIDDEN * CC];
__device__ __nv_bfloat16 g_wf2_h[(size_t)CC * HIDDEN], g_wf2_l[(size_t)CC * HIDDEN];

// ---------------------------------------------------------------------------
// Helpers
// ---------------------------------------------------------------------------
__device__ __forceinline__ float gelu_exact(float v) {
    return 0.5f * v * (1.0f + erff(v * 0.7071067811865475f));
}

__device__ __forceinline__ void f2hl(float x, __nv_bfloat16& h, __nv_bfloat16& l) {
    h = __float2bfloat16(x);
    l = __float2bfloat16(x - __bfloat162float(h));
}

__device__ __forceinline__ uint32_t smem_u32(const void* p) {
    uint32_t a;
    asm("{ .reg .u64 t; cvta.to.shared.u64 t, %1; cvt.u32.u64 %0, t; }" : "=r"(a) : "l"(p));
    return a;
}

__device__ __forceinline__ void cpasync16(uint32_t dst, const void* src) {
    asm volatile("cp.async.cg.shared.global [%0], [%1], 16;" :: "r"(dst), "l"(src));
}
#define CP_COMMIT() asm volatile("cp.async.commit_group;" ::: "memory")
#define CP_WAIT0()  asm volatile("cp.async.wait_group 0;" ::: "memory")

__device__ __forceinline__ void ldm4(uint32_t* r, uint32_t addr) {
    asm volatile("ldmatrix.sync.aligned.m8n8.x4.shared.b16 {%0,%1,%2,%3}, [%4];"
                 : "=r"(r[0]), "=r"(r[1]), "=r"(r[2]), "=r"(r[3]) : "r"(addr));
}

__device__ __forceinline__ void mma16816(float* d, const uint32_t* a, const uint32_t* b) {
    asm volatile(
        "mma.sync.aligned.m16n8k16.row.col.f32.bf16.bf16.f32 "
        "{%0,%1,%2,%3}, {%4,%5,%6,%7}, {%8,%9}, {%0,%1,%2,%3};"
        : "+f"(d[0]), "+f"(d[1]), "+f"(d[2]), "+f"(d[3])
        : "r"(a[0]), "r"(a[1]), "r"(a[2]), "r"(a[3]), "r"(b[0]), "r"(b[1]));
}

// ---------------------------------------------------------------------------
// Split-bf16 HMMA NT GEMM (identical to the passing Round-4 kernel).
// ---------------------------------------------------------------------------
#define BUFSZ  40960u
#define OFF_AH 0u
#define OFF_AL 10240u
#define OFF_BH 20480u
#define OFF_BL 30720u
#define GEMM_SMEM (2 * BUFSZ)

template<int EPI, int OUT>
__global__ void __launch_bounds__(256)
gemm_mma(const __nv_bfloat16* __restrict__ Ahg, const __nv_bfloat16* __restrict__ Alg,
         const __nv_bfloat16* __restrict__ Bhg, const __nv_bfloat16* __restrict__ Blg,
         const float* __restrict__ bias,
         float* __restrict__ C,
         __nv_bfloat16* __restrict__ Ch, __nv_bfloat16* __restrict__ Cl,
         const float* __restrict__ resid,
         int M, int N, int K)
{
    extern __shared__ char smem[];
    const uint32_t sb = smem_u32(smem);

    const int tid  = threadIdx.x;
    const int wid  = tid >> 5;
    const int lane = tid & 31;
    const int row0 = blockIdx.y * 128;
    const int col0 = blockIdx.x * 128;
    const int KT   = K >> 5;

    float acc[4][4][4];
    #pragma unroll
    for (int a = 0; a < 4; a++)
        #pragma unroll
        for (int b = 0; b < 4; b++)
            #pragma unroll
            for (int c = 0; c < 4; c++) acc[a][b][c] = 0.0f;

    auto load_stage = [&](int kt, int buf) {
        const int kw = kt * 32;
        const uint32_t dstb = sb + buf * BUFSZ;
        #pragma unroll
        for (int q = 0; q < 4; q++) {
            int cid = q * 256 + tid;
            int arr = cid >> 9;
            int idx = cid & 511;
            int row = idx >> 2, ch = idx & 3;
            int ar  = min(row0 + row, M - 1);
            const __nv_bfloat16* src = (arr ? Alg : Ahg) + (size_t)ar * K + kw + ch * 8;
            cpasync16(dstb + (arr ? OFF_AL : OFF_AH) + row * 80u + ch * 16u, src);
        }
        #pragma unroll
        for (int q = 0; q < 4; q++) {
            int cid = q * 256 + tid;
            int arr = cid >> 9;
            int idx = cid & 511;
            int row = idx >> 2, ch = idx & 3;
            const __nv_bfloat16* src = (arr ? Blg : Bhg) + (size_t)(col0 + row) * K + kw + ch * 8;
            cpasync16(dstb + (arr ? OFF_BL : OFF_BH) + row * 80u + ch * 16u, src);
        }
        CP_COMMIT();
    };

    load_stage(0, 0);
    CP_WAIT0();
    __syncthreads();

    const int m0w = (wid & 1) * 64;
    const int n0w = (wid >> 1) * 32;
    const uint32_t a_off = (uint32_t)(m0w + (lane & 15)) * 80u + (uint32_t)((lane >> 4) << 4);
    const uint32_t b_off = (uint32_t)(n0w + (lane & 7) + ((lane >> 4) << 3)) * 80u
                         + (uint32_t)(((lane >> 3) & 1) << 4);

    for (int kt = 0; kt < KT; kt++) {
        const int buf = kt & 1;
        if (kt + 1 < KT) load_stage(kt + 1, buf ^ 1);

        const uint32_t bb = sb + buf * BUFSZ;
        #pragma unroll
        for (int s = 0; s < 2; s++) {
            uint32_t ah[4][4], al[4][4], bh[4][2], bl[4][2];
            #pragma unroll
            for (int mi = 0; mi < 4; mi++) {
                ldm4(ah[mi], bb + OFF_AH + a_off + mi * 1280u + s * 32u);
                ldm4(al[mi], bb + OFF_AL + a_off + mi * 1280u + s * 32u);
            }
            #pragma unroll
            for (int nj = 0; nj < 2; nj++) {
                uint32_t t[4];
                ldm4(t, bb + OFF_BH + b_off + nj * 1280u + s * 32u);
                bh[nj*2][0] = t[0]; bh[nj*2][1] = t[1];
                bh[nj*2+1][0] = t[2]; bh[nj*2+1][1] = t[3];
                ldm4(t, bb + OFF_BL + b_off + nj * 1280u + s * 32u);
                bl[nj*2][0] = t[0]; bl[nj*2][1] = t[1];
                bl[nj*2+1][0] = t[2]; bl[nj*2+1][1] = t[3];
            }
            #pragma unroll
            for (int mi = 0; mi < 4; mi++)
                #pragma unroll
                for (int nj = 0; nj < 4; nj++) {
                    mma16816(acc[mi][nj], ah[mi], bh[nj]);
                    mma16816(acc[mi][nj], ah[mi], bl[nj]);
                    mma16816(acc[mi][nj], al[mi], bh[nj]);
                }
        }
        CP_WAIT0();
        __syncthreads();
    }

    #pragma unroll
    for (int mi = 0; mi < 4; mi++) {
        const int rbase = row0 + m0w + mi * 16 + (lane >> 2);
        #pragma unroll
        for (int half = 0; half < 2; half++) {
            const int m = rbase + half * 8;
            if (m >= M) continue;
            #pragma unroll
            for (int nj = 0; nj < 4; nj++) {
                const int n = col0 + n0w + nj * 8 + (lane & 3) * 2;
                float v0 = acc[mi][nj][half * 2 + 0] + bias[n];
                float v1 = acc[mi][nj][half * 2 + 1] + bias[n + 1];
                if (EPI == 1) { v0 = gelu_exact(v0); v1 = gelu_exact(v1); }
                if (EPI == 2) {
                    const float* rs = resid + (size_t)(m + m / 1568 + 1) * CC + n;
                    v0 += rs[0]; v1 += rs[1];
                }
                if (OUT == 0) {
                    float* cp = C + (size_t)m * N + n;
                    if (EPI == 3) {
                        float2 old = *(const float2*)cp;
                        v0 += old.x; v1 += old.y;
                    }
                    float2 o = {v0, v1};
                    *(float2*)cp = o;
                } else {
                    __nv_bfloat16 h0, l0, h1, l1;
                    f2hl(v0, h0, l0);
                    f2hl(v1, h1, l1);
                    *(__nv_bfloat162*)(Ch + (size_t)m * N + n) = __halves2bfloat162(h0, h1);
                    *(__nv_bfloat162*)(Cl + (size_t)m * N + n) = __halves2bfloat162(l0, l1);
                }
            }
        }
    }
}

// ---------------------------------------------------------------------------
// Fused weight conversion: all 7 weights -> hi/lo bf16 in one launch.
// ---------------------------------------------------------------------------
struct WSegs {
    const float4*   src[7];
    __nv_bfloat162* dh[7];
    __nv_bfloat162* dl[7];
    int             n4[7];
};

__global__ void conv_all(WSegs w, int total4)
{
    int i = blockIdx.x * blockDim.x + threadIdx.x;
    if (i >= total4) return;
    int rem = i;
    #pragma unroll
    for (int s = 0; s < 7; s++) {
        if (rem < w.n4[s]) {
            float4 v = w.src[s][rem];
            __nv_bfloat16 h0, l0, h1, l1, h2, l2, h3, l3;
            f2hl(v.x, h0, l0); f2hl(v.y, h1, l1);
            f2hl(v.z, h2, l2); f2hl(v.w, h3, l3);
            w.dh[s][rem * 2 + 0] = __halves2bfloat162(h0, h1);
            w.dh[s][rem * 2 + 1] = __halves2bfloat162(h2, h3);
            w.dl[s][rem * 2 + 0] = __halves2bfloat162(l0, l1);
            w.dl[s][rem * 2 + 1] = __halves2bfloat162(l2, l3);
            return;
        }
        rem -= w.n4[s];
    }
}

// ---------------------------------------------------------------------------
// LayerNorm over 768 (=256*3). One block/row. Writes hi/lo bf16.
// ---------------------------------------------------------------------------
__global__ void ln_kernel(const float* __restrict__ src0,
                          const float* __restrict__ xt,
                          const float* __restrict__ g,
                          const float* __restrict__ bta,
                          __nv_bfloat16* __restrict__ oh,
                          __nv_bfloat16* __restrict__ ol, int mode)
{
    int m = blockIdx.x;
    const float* src;
    if (mode == 0) {
        src = src0 + (size_t)(m + m / 1568 + 1) * CC;
    } else if (mode == 1) {
        int sb = m / SL, p = m % SL;
        int b = sb >> 3, t = sb & 7;
        if (p == 0) src = src0 + (size_t)b * NTOK * CC;
        else        src = xt + ((size_t)(b * HW + (p - 1)) * TT + t) * CC;
    } else {
        src = src0 + (size_t)m * CC;
    }
    int tid = threadIdx.x;
    float v0 = src[tid], v1 = src[tid + 256], v2 = src[tid + 512];
    float s = v0 + v1 + v2;
    __shared__ float sh[32];
    int lane = tid & 31, wid = tid >> 5;
    #pragma unroll
    for (int o = 16; o; o >>= 1) s += __shfl_xor_sync(0xffffffffu, s, o);
    if (lane == 0) sh[wid] = s;
    __syncthreads();
    if (wid == 0) {
        float t2 = (lane < 8) ? sh[lane] : 0.0f;
        #pragma unroll
        for (int o = 4; o; o >>= 1) t2 += __shfl_xor_sync(0xffffffffu, t2, o);
        if (lane == 0) sh[0] = t2;
    }
    __syncthreads();
    float mean = sh[0] * (1.0f / 768.0f);
    __syncthreads();
    float d0 = v0 - mean, d1 = v1 - mean, d2 = v2 - mean;
    float s2 = d0 * d0 + d1 * d1 + d2 * d2;
    #pragma unroll
    for (int o = 16; o; o >>= 1) s2 += __shfl_xor_sync(0xffffffffu, s2, o);
    if (lane == 0) sh[wid] = s2;
    __syncthreads();
    if (wid == 0) {
        float t2 = (lane < 8) ? sh[lane] : 0.0f;
        #pragma unroll
        for (int o = 4; o; o >>= 1) t2 += __shfl_xor_sync(0xffffffffu, t2, o);
        if (lane == 0) sh[0] = t2;
    }
    __syncthreads();
    float inv = rsqrtf(sh[0] * (1.0f / 768.0f) + 1e-5f);
    size_t ob = (size_t)m * CC;
    #pragma unroll
    for (int p = 0; p < 3; p++) {
        float d = (p == 0) ? d0 : (p == 1) ? d1 : d2;
        int c = tid + p * 256;
        float v = d * inv * g[c] + bta[c];
        __nv_bfloat16 h, l;
        f2hl(v, h, l);
        oh[ob + c] = h;
        ol[ob + c] = l;
    }
}

// ---------------------------------------------------------------------------
// Temporal attention: fused per (seq, head). Padded smem (conflict-free).
// ---------------------------------------------------------------------------
__global__ void temporal_attn(const float* __restrict__ qkv,
                              __nv_bfloat16* __restrict__ oh,
                              __nv_bfloat16* __restrict__ ol)
{
    int seq = blockIdx.x, h = blockIdx.y;
    __shared__ float q[TT][HD + 1], k[TT][HD + 1], v[TT][HD + 1], p[TT][TT];
    int tid = threadIdx.x;
    size_t base = (size_t)(seq * TT) * C3 + h * HD;
    #pragma unroll
    for (int t = 0; t < TT; t++) {
        q[t][tid] = qkv[base + (size_t)t * C3 + tid];
        k[t][tid] = qkv[base + (size_t)t * C3 + CC + tid];
        v[t][tid] = qkv[base + (size_t)t * C3 + 2 * CC + tid];
    }
    __syncthreads();
    int i = tid >> 3, j = tid & 7;
    float s = 0.0f;
    #pragma unroll
    for (int d = 0; d < HD; d++) s = fmaf(q[i][d], k[j][d], s);
    p[i][j] = s * 0.125f;
    __syncthreads();
    if (tid < TT) {
        float mx = -1e30f;
        #pragma unroll
        for (int jj = 0; jj < TT; jj++) mx = fmaxf(mx, p[tid][jj]);
        float sum = 0.0f;
        #pragma unroll
        for (int jj = 0; jj < TT; jj++) {
            float e = expf(p[tid][jj] - mx);
            p[tid][jj] = e; sum += e;
        }
        float invs = 1.0f / sum;
        #pragma unroll
        for (int jj = 0; jj < TT; jj++) p[tid][jj] *= invs;
    }
    __syncthreads();
    #pragma unroll
    for (int t = 0; t < TT; t++) {
        float o = 0.0f;
        #pragma unroll
        for (int jj = 0; jj < TT; jj++) o = fmaf(p[t][jj], v[jj][tid], o);
        __nv_bfloat16 hh, ll;
        f2hl(o, hh, ll);
        size_t oi = (size_t)(seq * TT + t) * CC + h * HD + tid;
        oh[oi] = hh;
        ol[oi] = ll;
    }
}

// ---------------------------------------------------------------------------
// Spatial scores: per z=(s,h): S = Q * K^T, 197x197x64.
// Tile 64x64x16, 256 threads, 4x4 microtile, float4 LDS.
// ---------------------------------------------------------------------------
__global__ void spatial_scores(const float* __restrict__ qkv, float* __restrict__ sc)
{
    int z = blockIdx.z, s = z / NH, h = z % NH;
    const float* Q  = qkv + (size_t)s * SL * C3 + h * HD;
    const float* Kp = Q + CC;
    float* S = sc + (size_t)z * SL2;
    __shared__ float Qs[16][68], Ks[16][68];
    int tid = threadIdx.x;
    int tx = tid & 15, ty = tid >> 4;
    int row0 = blockIdx.y * 64, col0 = blockIdx.x * 64;
    float acc[4][4] = {};
    int lr = tid >> 2;          // 0..63
    int lc = (tid & 3) << 2;    // 0,4,8,12
    #pragma unroll
    for (int k0 = 0; k0 < HD; k0 += 16) {
        #pragma unroll
        for (int u = 0; u < 4; u++) {
            int gr = row0 + lr;
            Qs[lc + u][lr] = (gr < SL) ? Q[(size_t)gr * C3 + k0 + lc + u] : 0.0f;
            int gc = col0 + lr;
            Ks[lc + u][lr] = (gc < SL) ? Kp[(size_t)gc * C3 + k0 + lc + u] : 0.0f;
        }
        __syncthreads();
        #pragma unroll
        for (int kk = 0; kk < 16; kk++) {
            float4 a4 = *(const float4*)&Qs[kk][ty * 4];
            float4 b4 = *(const float4*)&Ks[kk][tx * 4];
            float a[4] = {a4.x, a4.y, a4.z, a4.w};
            float b[4] = {b4.x, b4.y, b4.z, b4.w};
            #pragma unroll
            for (int i = 0; i < 4; i++)
                #pragma unroll
                for (int j = 0; j < 4; j++)
                    acc[i][j] = fmaf(a[i], b[j], acc[i][j]);
        }
        __syncthreads();
    }
    #pragma unroll
    for (int i = 0; i < 4; i++) {
        int m = row0 + ty * 4 + i;
        if (m >= SL) continue;
        #pragma unroll
        for (int j = 0; j < 4; j++) {
            int n = col0 + tx * 4 + j;
            if (n < SL) S[(size_t)m * SL + n] = acc[i][j];
        }
    }
}

// ---------------------------------------------------------------------------
// Softmax over rows of length 197 (1/8 scale folded in).
// ---------------------------------------------------------------------------
__global__ void softmax197(float* __restrict__ sc, int nrows)
{
    int row = blockIdx.x * 8 + (threadIdx.x >> 5);
    if (row >= nrows) return;
    int lane = threadIdx.x & 31;
    float* r = sc + (size_t)row * SL;
    float mx = -1e30f;
    for (int j = lane; j < SL; j += 32) mx = fmaxf(mx, r[j] * 0.125f);
    #pragma unroll
    for (int o = 16; o; o >>= 1) mx = fmaxf(mx, __shfl_xor_sync(0xffffffffu, mx, o));
    float sum = 0.0f;
    for (int j = lane; j < SL; j += 32) {
        float e = expf(r[j] * 0.125f - mx);
        r[j] = e; sum += e;
    }
    #pragma unroll
    for (int o = 16; o; o >>= 1) sum += __shfl_xor_sync(0xffffffffu, sum, o);
    float inv = 1.0f / sum;
    for (int j = lane; j < SL; j += 32) r[j] *= inv;
}

// ---------------------------------------------------------------------------
// Spatial P*V: per z: O = P(197x197) * V(197x64). Writes hi/lo bf16.
// Tile 64(M)x64(N)x16, 256 threads, 4x4 microtile.
// ---------------------------------------------------------------------------
__global__ void spatial_pv(const float* __restrict__ sc, const float* __restrict__ qkv,
                           __nv_bfloat16* __restrict__ oh, __nv_bfloat16* __restrict__ ol)
{
    int z = blockIdx.z, s = z / NH, h = z % NH;
    const float* P = sc + (size_t)z * SL2;
    const float* V = qkv + (size_t)s * SL * C3 + 2 * CC + h * HD;
    size_t obase = (size_t)s * SL * CC + h * HD;
    __shared__ float Ps[16][68], Vs[16][68];
    int tid = threadIdx.x;
    int tx = tid & 15, ty = tid >> 4;
    int row0 = blockIdx.y * 64;
    float acc[4][4] = {};
    int lrp = tid >> 2, lcp = (tid & 3) << 2;   // P: 64 rows x 16 k
    int lrv = tid >> 4, lcv = (tid & 15) << 2;  // V: 16 k x 64 cols
    for (int k0 = 0; k0 < SL; k0 += 16) {
        #pragma unroll
        for (int u = 0; u < 4; u++) {
            int gm = row0 + lrp, gk = k0 + lcp + u;
            Ps[lcp + u][lrp] = (gm < SL && gk < SL) ? P[(size_t)gm * SL + gk] : 0.0f;
        }
        {
            int gk = k0 + lrv;
            #pragma unroll
            for (int u = 0; u < 4; u++)
                Vs[lrv][lcv + u] = (gk < SL) ? V[(size_t)gk * C3 + lcv + u] : 0.0f;
        }
        __syncthreads();
        #pragma unroll
        for (int kk = 0; kk < 16; kk++) {
            float4 a4 = *(const float4*)&Ps[kk][ty * 4];
            float4 b4 = *(const float4*)&Vs[kk][tx * 4];
            float a[4] = {a4.x, a4.y, a4.z, a4.w};
            float b[4] = {b4.x, b4.y, b4.z, b4.w};
            #pragma unroll
            for (int i = 0; i < 4; i++)
                #pragma unroll
                for (int j = 0; j < 4; j++)
                    acc[i][j] = fmaf(a[i], b[j], acc[i][j]);
        }
        __syncthreads();
    }
    #pragma unroll
    for (int i = 0; i < 4; i++) {
        int m = row0 + ty * 4 + i;
        if (m >= SL) continue;
        #pragma unroll
        for (int j = 0; j < 4; j++) {
            __nv_bfloat16 hh, ll;
            f2hl(acc[i][j], hh, ll);
            size_t oi = obase + (size_t)m * CC + tx * 4 + j;
            oh[oi] = hh;
            ol[oi] = ll;
        }
    }
}

// ---------------------------------------------------------------------------
// Assemble x_new into d_out
// ---------------------------------------------------------------------------
__global__ void assemble(const float* __restrict__ x, const float* __restrict__ xt,
                         const float* __restrict__ ps, float* __restrict__ out)
{
    int row = blockIdx.x;
    int b = row / NTOK, n = row % NTOK;
    size_t orow = (size_t)row * CC;
    if (n == 0) {
        for (int c = threadIdx.x; c < CC; c += 256) {
            float acc = 0.0f;
            #pragma unroll
            for (int t = 0; t < TT; t++)
                acc += ps[((size_t)(b * TT + t) * SL) * CC + c];
            out[orow + c] = x[orow + c] + acc * 0.125f;
        }
    } else {
        int r = n - 1, hw = r >> 3, t = r & 7;
        size_t xtrow = ((size_t)b * 1568 + r) * CC;
        size_t psrow = ((size_t)((b * TT + t) * SL + 1 + hw)) * CC;
        for (int c = threadIdx.x; c < CC; c += 256)
            out[orow + c] = xt[xtrow + c] + ps[psrow + c];
    }
}

// ---------------------------------------------------------------------------
// Host launch
// ---------------------------------------------------------------------------
extern "C" void kernel_launch(void* const* d_in, const int* in_sizes, int n_in,
                              void* d_out, int out_size)
{
    const float* x        = (const float*)d_in[0];
    const float* ln_t_g   = (const float*)d_in[1];
    const float* ln_t_b   = (const float*)d_in[2];
    const float* t_qkv_w  = (const float*)d_in[3];
    const float* t_qkv_b  = (const float*)d_in[4];
    const float* t_proj_w = (const float*)d_in[5];
    const float* t_proj_b = (const float*)d_in[6];
    const float* t_fc_w   = (const float*)d_in[7];
    const float* t_fc_b   = (const float*)d_in[8];
    const float* ln1_g    = (const float*)d_in[9];
    const float* ln1_b    = (const float*)d_in[10];
    const float* s_qkv_w  = (const float*)d_in[11];
    const float* s_qkv_b  = (const float*)d_in[12];
    const float* s_proj_w = (const float*)d_in[13];
    const float* s_proj_b = (const float*)d_in[14];
    const float* ln2_g    = (const float*)d_in[15];
    const float* ln2_b    = (const float*)d_in[16];
    const float* fc1_w    = (const float*)d_in[17];
    const float* fc1_b    = (const float*)d_in[18];
    const float* fc2_w    = (const float*)d_in[19];
    const float* fc2_b    = (const float*)d_in[20];
    float* out = (float*)d_out;

    float *qkv, *xt, *sc, *proj;
    __nv_bfloat16 *lnh, *lnl, *ath, *atl, *pjh, *pjl, *f1h, *f1l;
    cudaGetSymbolAddress((void**)&qkv,  g_qkv);
    cudaGetSymbolAddress((void**)&xt,   g_xt);
    cudaGetSymbolAddress((void**)&sc,   g_sc);
    cudaGetSymbolAddress((void**)&proj, g_proj);
    cudaGetSymbolAddress((void**)&lnh,  g_ln_h);
    cudaGetSymbolAddress((void**)&lnl,  g_ln_l);
    cudaGetSymbolAddress((void**)&ath,  g_at_h);
    cudaGetSymbolAddress((void**)&atl,  g_at_l);
    cudaGetSymbolAddress((void**)&pjh,  g_pj_h);
    cudaGetSymbolAddress((void**)&pjl,  g_pj_l);
    cudaGetSymbolAddress((void**)&f1h,  g_f1_h);
    cudaGetSymbolAddress((void**)&f1l,  g_f1_l);

    __nv_bfloat16 *wtq_h, *wtq_l, *wtp_h, *wtp_l, *wtf_h, *wtf_l;
    __nv_bfloat16 *wsq_h, *wsq_l, *wsp_h, *wsp_l, *wf1_h, *wf1_l, *wf2_h, *wf2_l;
    cudaGetSymbolAddress((void**)&wtq_h, g_wtq_h); cudaGetSymbolAddress((void**)&wtq_l, g_wtq_l);
    cudaGetSymbolAddress((void**)&wtp_h, g_wtp_h); cudaGetSymbolAddress((void**)&wtp_l, g_wtp_l);
    cudaGetSymbolAddress((void**)&wtf_h, g_wtf_h); cudaGetSymbolAddress((void**)&wtf_l, g_wtf_l);
    cudaGetSymbolAddress((void**)&wsq_h, g_wsq_h); cudaGetSymbolAddress((void**)&wsq_l, g_wsq_l);
    cudaGetSymbolAddress((void**)&wsp_h, g_wsp_h); cudaGetSymbolAddress((void**)&wsp_l, g_wsp_l);
    cudaGetSymbolAddress((void**)&wf1_h, g_wf1_h); cudaGetSymbolAddress((void**)&wf1_l, g_wf1_l);
    cudaGetSymbolAddress((void**)&wf2_h, g_wf2_h); cudaGetSymbolAddress((void**)&wf2_l, g_wf2_l);

    cudaFuncSetAttribute(gemm_mma<0,0>, cudaFuncAttributeMaxDynamicSharedMemorySize, GEMM_SMEM);
    cudaFuncSetAttribute(gemm_mma<0,1>, cudaFuncAttributeMaxDynamicSharedMemorySize, GEMM_SMEM);
    cudaFuncSetAttribute(gemm_mma<1,1>, cudaFuncAttributeMaxDynamicSharedMemorySize, GEMM_SMEM);
    cudaFuncSetAttribute(gemm_mma<2,0>, cudaFuncAttributeMaxDynamicSharedMemorySize, GEMM_SMEM);
    cudaFuncSetAttribute(gemm_mma<3,0>, cudaFuncAttributeMaxDynamicSharedMemorySize, GEMM_SMEM);

    // 0. convert all weights in one launch
    {
        WSegs w;
        w.src[0] = (const float4*)t_qkv_w;  w.dh[0] = (__nv_bfloat162*)wtq_h; w.dl[0] = (__nv_bfloat162*)wtq_l; w.n4[0] = C3 * CC / 4;
        w.src[1] = (const float4*)t_proj_w; w.dh[1] = (__nv_bfloat162*)wtp_h; w.dl[1] = (__nv_bfloat162*)wtp_l; w.n4[1] = CC * CC / 4;
        w.src[2] = (const float4*)t_fc_w;   w.dh[2] = (__nv_bfloat162*)wtf_h; w.dl[2] = (__nv_bfloat162*)wtf_l; w.n4[2] = CC * CC / 4;
        w.src[3] = (const float4*)s_qkv_w;  w.dh[3] = (__nv_bfloat162*)wsq_h; w.dl[3] = (__nv_bfloat162*)wsq_l; w.n4[3] = C3 * CC / 4;
        w.src[4] = (const float4*)s_proj_w; w.dh[4] = (__nv_bfloat162*)wsp_h; w.dl[4] = (__nv_bfloat162*)wsp_l; w.n4[4] = CC * CC / 4;
        w.src[5] = (const float4*)fc1_w;    w.dh[5] = (__nv_bfloat162*)wf1_h; w.dl[5] = (__nv_bfloat162*)wf1_l; w.n4[5] = HIDDEN * CC / 4;
        w.src[6] = (const float4*)fc2_w;    w.dh[6] = (__nv_bfloat162*)wf2_h; w.dl[6] = (__nv_bfloat162*)wf2_l; w.n4[6] = CC * HIDDEN / 4;
        int total4 = 0;
        for (int i = 0; i < 7; i++) total4 += w.n4[i];
        conv_all<<<(total4 + 255) / 256, 256>>>(w, total4);
    }

    // 1. temporal LN (skip cls) -> hi/lo
    ln_kernel<<<MT, 256>>>(x, nullptr, ln_t_g, ln_t_b, lnh, lnl, 0);

    // 2. temporal qkv -> fp32
    gemm_mma<0,0><<<dim3(C3/128, (MT+127)/128), 256, GEMM_SMEM>>>(
        lnh, lnl, wtq_h, wtq_l, t_qkv_b, qkv, nullptr, nullptr, nullptr, MT, C3, CC);

    // 3. temporal attention -> hi/lo
    temporal_attn<<<dim3(BB * HW, NH), 64>>>(qkv, ath, atl);

    // 4. temporal proj -> hi/lo
    gemm_mma<0,1><<<dim3(CC/128, (MT+127)/128), 256, GEMM_SMEM>>>(
        ath, atl, wtp_h, wtp_l, t_proj_b, nullptr, pjh, pjl, nullptr, MT, CC, CC);

    // 5. t_fc + residual from x (skip-cls) -> fp32 xt
    gemm_mma<2,0><<<dim3(CC/128, (MT+127)/128), 256, GEMM_SMEM>>>(
        pjh, pjl, wtf_h, wtf_l, t_fc_b, xt, nullptr, nullptr, x, MT, CC, CC);

    // 6. spatial gather + LN1 -> hi/lo
    ln_kernel<<<MS, 256>>>(x, xt, ln1_g, ln1_b, lnh, lnl, 1);

    // 7. spatial qkv -> fp32
    gemm_mma<0,0><<<dim3(C3/128, (MS+127)/128), 256, GEMM_SMEM>>>(
        lnh, lnl, wsq_h, wsq_l, s_qkv_b, qkv, nullptr, nullptr, nullptr, MS, C3, CC);

    // 8-10. spatial attention -> hi/lo
    spatial_scores<<<dim3(4, 4, ZB), 256>>>(qkv, sc);
    softmax197<<<(ZB * SL + 7) / 8, 256>>>(sc, ZB * SL);
    spatial_pv<<<dim3(1, 4, ZB), 256>>>(sc, qkv, ath, atl);

    // 11. spatial proj -> fp32
    gemm_mma<0,0><<<dim3(CC/128, (MS+127)/128), 256, GEMM_SMEM>>>(
        ath, atl, wsp_h, wsp_l, s_proj_b, proj, nullptr, nullptr, nullptr, MS, CC, CC);

    // 12. assemble x_new into d_out
    assemble<<<MX, 256>>>(x, xt, proj, out);

    // 13. LN2 -> hi/lo
    ln_kernel<<<MX, 256>>>(out, nullptr, ln2_g, ln2_b, lnh, lnl, 2);

    // 14. fc1 + gelu -> hi/lo
    gemm_mma<1,1><<<dim3(HIDDEN/128, (MX+127)/128), 256, GEMM_SMEM>>>(
        lnh, lnl, wf1_h, wf1_l, fc1_b, nullptr, f1h, f1l, nullptr, MX, HIDDEN, CC);

    // 15. fc2 + in-place residual on d_out
    gemm_mma<3,0><<<dim3(CC/128, (MX+127)/128), 256, GEMM_SMEM>>>(
        f1h, f1l, wf2_h, wf2_l, fc2_b, out, nullptr, nullptr, nullptr, MX, CC, HIDDEN);
}